// round 12
// baseline (speedup 1.0000x reference)
#include <cuda_runtime.h>
#include <cuda_fp16.h>
#include <cstdint>
#include <math.h>

#define B_  2
#define L_  2048
#define C_  1024
#define H_  16
#define HD_ 64
#define FF_ 4096
#define ROWS (B_*L_)          // 4096
#define SCALE_ 0.125f         // 64^-0.5
#define EPS_ 1e-5f

// ---------------- scratch (allocation-free rule: __device__ globals) --------
__device__ __half g_xn  [ROWS*C_];        // LN1 out, half, permh layout
__device__ float  g_qkv [ROWS*3*C_];      // qkv proj out, fp32
__device__ __half g_fbg [ROWS*C_];        // fb1 out, half, permh
__device__ float  g_fb2 [ROWS*C_];        // fb @ fp_w2, fp32
__device__ __half g_Qe  [B_*H_*L_*128];   // half, permh layout
__device__ __half g_Ke  [B_*H_*L_*128];   // half, permh layout
__device__ __half g_Vt  [B_*H_*HD_*L_];   // half, [bh][64][L], permh on l%16
__device__ __half g_O   [ROWS*C_];        // attn out, half, permh
__device__ float  g_xmid[ROWS*C_];        // fp32
__device__ __half g_xn2 [ROWS*C_];        // LN2 out, half, permh
__device__ __half g_h   [ROWS*FF_];       // mlp hidden, half, permh
// transposed half weights [N][K], permh on k
__device__ __half g_wt_qkv[3*C_*C_];
__device__ __half g_wt_fp2[C_*C_];
__device__ __half g_wt_out[C_*C_];
__device__ __half g_wt_m1 [FF_*C_];
__device__ __half g_wt_m2 [C_*FF_];

__device__ __forceinline__ float gelu_exact(float v) {
    return 0.5f * v * (1.0f + erff(v * 0.70710678118654752f));
}
__device__ __forceinline__ void cp16(void* smem_dst, const void* gmem_src) {
    unsigned int s = (unsigned int)__cvta_generic_to_shared(smem_dst);
    asm volatile("cp.async.cg.shared.global [%0], [%1], 16;" :: "r"(s), "l"(gmem_src));
}
// fp16 layout interleave within 16: (2g,2g+1,2g+8,2g+9) contiguous at 4g
__device__ __forceinline__ int permh(int k) {
    return (k & ~15) | (k & 1) | (((k >> 3) & 1) << 1) | (((k >> 1) & 3) << 2);
}
#define MMA_F16(c0,c1,c2,c3,a0,a1,a2,a3,b0,b1) \
    asm volatile("mma.sync.aligned.m16n8k16.row.col.f32.f16.f16.f32 " \
        "{%0,%1,%2,%3}, {%4,%5,%6,%7}, {%8,%9}, {%0,%1,%2,%3};" \
        : "+f"(c0), "+f"(c1), "+f"(c2), "+f"(c3) \
        : "r"(a0), "r"(a1), "r"(a2), "r"(a3), "r"(b0), "r"(b1))

// ------- merged weight transpose + fp16 convert (+permh on k) ---------------
#define T_QKV (32*96)
#define T_FP2 (32*32)
#define T_OUT (32*32)
#define T_M1  (32*128)
#define T_M2  (128*32)
#define T_TOT (T_QKV + T_FP2 + T_OUT + T_M1 + T_M2)
__global__ void wtrans_all(const float* __restrict__ qkv_w, const float* __restrict__ fp_w2,
                           const float* __restrict__ out_w, const float* __restrict__ m1_w,
                           const float* __restrict__ m2_w,
                           __half* __restrict__ t_qkv, __half* __restrict__ t_fp2,
                           __half* __restrict__ t_out, __half* __restrict__ t_m1,
                           __half* __restrict__ t_m2) {
    __shared__ float t[32][33];
    int bid = blockIdx.x;
    const float* W; __half* Wt; int K, N, tile;
    if (bid < T_QKV)                    { W = qkv_w; Wt = t_qkv; K = C_;  N = 3*C_; tile = bid; }
    else if ((bid -= T_QKV) < T_FP2)    { W = fp_w2; Wt = t_fp2; K = C_;  N = C_;   tile = bid; }
    else if ((bid -= T_FP2) < T_OUT)    { W = out_w; Wt = t_out; K = C_;  N = C_;   tile = bid; }
    else if ((bid -= T_OUT) < T_M1)     { W = m1_w;  Wt = t_m1;  K = C_;  N = FF_;  tile = bid; }
    else { bid -= T_M1;                   W = m2_w;  Wt = t_m2;  K = FF_; N = C_;   tile = bid; }
    int ntiles_n = N / 32;
    int k0 = (tile / ntiles_n) * 32;
    int n0 = (tile % ntiles_n) * 32;
    int tx = threadIdx.x, ty = threadIdx.y;
    #pragma unroll
    for (int j = 0; j < 4; j++) {
        int k = k0 + ty + j * 8;
        t[ty + j * 8][tx] = W[(size_t)k * N + n0 + tx];
    }
    __syncthreads();
    int kdst = permh(k0 + tx);
    #pragma unroll
    for (int j = 0; j < 4; j++) {
        int nn = n0 + ty + j * 8;
        Wt[(size_t)nn * K + kdst] = __float2half_rn(t[tx][ty + j * 8]);
    }
}

// ---------------- LayerNorm -> half, permh layout ---------------------------
__global__ void ln_kernel(const float* __restrict__ X, const float* __restrict__ g,
                          const float* __restrict__ b, __half* __restrict__ Y) {
    int row = blockIdx.x;
    int tid = threadIdx.x;
    const float4* xr = (const float4*)(X + (size_t)row * C_);
    float4 t = xr[tid];
    float s  = t.x + t.y + t.z + t.w;
    float sq = t.x*t.x + t.y*t.y + t.z*t.z + t.w*t.w;
    #pragma unroll
    for (int o = 16; o; o >>= 1) {
        s  += __shfl_xor_sync(0xffffffffu, s,  o);
        sq += __shfl_xor_sync(0xffffffffu, sq, o);
    }
    __shared__ float ws[8], wq[8];
    __shared__ float mean_s, rstd_s;
    int w = tid >> 5;
    if ((tid & 31) == 0) { ws[w] = s; wq[w] = sq; }
    __syncthreads();
    if (tid == 0) {
        float S = 0.f, Q = 0.f;
        #pragma unroll
        for (int i = 0; i < 8; i++) { S += ws[i]; Q += wq[i]; }
        float mean = S * (1.0f / C_);
        float var  = Q * (1.0f / C_) - mean * mean;
        mean_s = mean; rstd_s = rsqrtf(var + EPS_);
    }
    __syncthreads();
    float mean = mean_s, rstd = rstd_s;
    float4 gg = ((const float4*)g)[tid];
    float4 bb = ((const float4*)b)[tid];
    __half2 p0 = __floats2half2_rn((t.x - mean) * rstd * gg.x + bb.x,
                                   (t.y - mean) * rstd * gg.y + bb.y);
    __half2 p1 = __floats2half2_rn((t.z - mean) * rstd * gg.z + bb.z,
                                   (t.w - mean) * rstd * gg.w + bb.w);
    __half* yr = Y + (size_t)row * C_;
    int c0 = tid * 4;
    *(__half2*)(yr + permh(c0))     = p0;
    *(__half2*)(yr + permh(c0 + 2)) = p1;
}

// ------- freq path stage 1: rank-1 outer + LN + GELU -> half permh ----------
__global__ void fb1_kernel(const float* __restrict__ fd, const float* __restrict__ w1,
                           const float* __restrict__ b1, const float* __restrict__ g,
                           const float* __restrict__ bln, __half* __restrict__ Y) {
    int row = blockIdx.x;
    int tid = threadIdx.x;
    float f = fd[row];
    float4 w = ((const float4*)w1)[tid];
    float4 bb = ((const float4*)b1)[tid];
    float4 t;
    t.x = f * w.x + bb.x; t.y = f * w.y + bb.y;
    t.z = f * w.z + bb.z; t.w = f * w.w + bb.w;
    float s  = t.x + t.y + t.z + t.w;
    float sq = t.x*t.x + t.y*t.y + t.z*t.z + t.w*t.w;
    #pragma unroll
    for (int o = 16; o; o >>= 1) {
        s  += __shfl_xor_sync(0xffffffffu, s,  o);
        sq += __shfl_xor_sync(0xffffffffu, sq, o);
    }
    __shared__ float ws[8], wqs[8];
    __shared__ float mean_s, rstd_s;
    int w5 = tid >> 5;
    if ((tid & 31) == 0) { ws[w5] = s; wqs[w5] = sq; }
    __syncthreads();
    if (tid == 0) {
        float S = 0.f, Q = 0.f;
        #pragma unroll
        for (int i = 0; i < 8; i++) { S += ws[i]; Q += wqs[i]; }
        float mean = S * (1.0f / C_);
        float var  = Q * (1.0f / C_) - mean * mean;
        mean_s = mean; rstd_s = rsqrtf(var + EPS_);
    }
    __syncthreads();
    float mean = mean_s, rstd = rstd_s;
    float4 gg = ((const float4*)g)[tid];
    float4 bl = ((const float4*)bln)[tid];
    __half2 p0 = __floats2half2_rn(gelu_exact((t.x - mean) * rstd * gg.x + bl.x),
                                   gelu_exact((t.y - mean) * rstd * gg.y + bl.y));
    __half2 p1 = __floats2half2_rn(gelu_exact((t.z - mean) * rstd * gg.z + bl.z),
                                   gelu_exact((t.w - mean) * rstd * gg.w + bl.w));
    __half* yr = Y + (size_t)row * C_;
    int c0 = tid * 4;
    *(__half2*)(yr + permh(c0))     = p0;
    *(__half2*)(yr + permh(c0 + 2)) = p1;
}

// ---- fp16 TC GEMM: 128x128 CTA, 64x32 warp tiles, BK=32, 3-stage, occ2 -----
#define BK_ 32
#define HSTR 48
#define A_STH (128*HSTR)
#define B_STH (128*HSTR)
#define STGH  (A_STH + B_STH)
#define GEMM_SMEM (3*STGH*2)       // 73728 B

__global__ __launch_bounds__(256, 2) void gemm_tc(
    const __half* __restrict__ A, const __half* __restrict__ Bt,
    const float* __restrict__ bias, const float* __restrict__ R,
    float* __restrict__ Cf, __half* __restrict__ Ch,
    int M, int N, int K, int act) {
    extern __shared__ __half smh[];
    int tid = threadIdx.x;
    int lane = tid & 31, wid = tid >> 5;
    int wm = wid & 1, wn = wid >> 1;
    int m0 = blockIdx.y * 128, n0 = blockIdx.x * 128;

    float c[4][4][4];
    #pragma unroll
    for (int mi = 0; mi < 4; mi++)
        #pragma unroll
        for (int ni = 0; ni < 4; ni++)
            #pragma unroll
            for (int q = 0; q < 4; q++) c[mi][ni][q] = 0.f;

    int NT = K / BK_;
    auto issue = [&](int t) {
        __half* As = smh + (t % 3) * STGH;
        __half* Bs = As + A_STH;
        int k0 = t * BK_;
        #pragma unroll
        for (int it = 0; it < 2; it++) {
            int i = tid + it * 256;
            int row = i >> 2, off = (i & 3) * 8;
            cp16(As + row * HSTR + off, A + (size_t)(m0 + row) * K + k0 + off);
            cp16(Bs + row * HSTR + off, Bt + (size_t)(n0 + row) * K + k0 + off);
        }
        asm volatile("cp.async.commit_group;");
    };
    issue(0);
    issue(1);

    int r = lane >> 2, g = lane & 3;
    for (int t = 0; t < NT; t++) {
        if (t + 1 < NT) asm volatile("cp.async.wait_group 1;");
        else            asm volatile("cp.async.wait_group 0;");
        __syncthreads();
        if (t + 2 < NT) issue(t + 2);

        const __half* As = smh + (t % 3) * STGH;
        const __half* Bs = As + A_STH;
        #pragma unroll
        for (int ks = 0; ks < 2; ks++) {
            uint2 alo[4], ahi[4], bb[4];
            #pragma unroll
            for (int mi = 0; mi < 4; mi++) {
                alo[mi] = ((const uint2*)(As + (wm * 64 + mi * 16 + r) * HSTR))[ks * 4 + g];
                ahi[mi] = ((const uint2*)(As + (wm * 64 + mi * 16 + r + 8) * HSTR))[ks * 4 + g];
            }
            #pragma unroll
            for (int ni = 0; ni < 4; ni++)
                bb[ni] = ((const uint2*)(Bs + (wn * 32 + ni * 8 + r) * HSTR))[ks * 4 + g];
            #pragma unroll
            for (int mi = 0; mi < 4; mi++)
                #pragma unroll
                for (int ni = 0; ni < 4; ni++)
                    MMA_F16(c[mi][ni][0], c[mi][ni][1], c[mi][ni][2], c[mi][ni][3],
                            alo[mi].x, ahi[mi].x, alo[mi].y, ahi[mi].y,
                            bb[ni].x, bb[ni].y);
        }
    }

    #pragma unroll
    for (int mi = 0; mi < 4; mi++) {
        int row0 = m0 + wm * 64 + mi * 16 + r;
        #pragma unroll
        for (int ni = 0; ni < 4; ni++) {
            int col = n0 + wn * 32 + ni * 8 + g * 2;
            float b0 = bias[col], b1 = bias[col + 1];
            #pragma unroll
            for (int half_ = 0; half_ < 2; half_++) {
                int row = row0 + half_ * 8;
                float v0 = c[mi][ni][half_ * 2 + 0] + b0;
                float v1 = c[mi][ni][half_ * 2 + 1] + b1;
                if (act == 1) { v0 = gelu_exact(v0); v1 = gelu_exact(v1); }
                if (R) {
                    v0 += R[(size_t)row * N + col];
                    v1 += R[(size_t)row * N + col + 1];
                }
                if (Ch) {
                    *(__half2*)(Ch + (size_t)row * N + permh(col)) = __floats2half2_rn(v0, v1);
                } else {
                    *(float2*)(Cf + (size_t)row * N + col) = make_float2(v0, v1);
                }
            }
        }
    }
}

// ------- build extended Q/K (half permh) and V-transposed (half) ------------
#define BE_SMEM ((4096 + 4096 + 4160) * 4 + 64 * 72 * 2)   // 58624 B
__global__ void build_ext_kernel(const float* __restrict__ qkv, const float* __restrict__ fb2,
                                 const float* __restrict__ wqw, const float* __restrict__ wqb,
                                 const float* __restrict__ wkw, const float* __restrict__ wkb,
                                 const float* __restrict__ fscale,
                                 __half* __restrict__ Qe, __half* __restrict__ Ke,
                                 __half* __restrict__ Vt) {
    extern __shared__ char dynsm[];
    float* swq = (float*)dynsm;                  // 64*64
    float* swk = swq + 4096;                     // 64*64
    float* sfb = swk + 4096;                     // 64*65
    __half* vstage = (__half*)(sfb + 4160);      // 64 d x 72 (l permh'd)
    int bh = blockIdx.y;
    int lt = blockIdx.x;
    int b = bh >> 4, h = bh & 15;
    int l0 = lt * 64;
    int tid = threadIdx.x;
    for (int i = tid; i < 4096; i += 256) { swq[i] = wqw[i]; swk[i] = wkw[i]; }
    for (int i = tid; i < 4096; i += 256) {
        int r = i >> 6, c = i & 63;
        sfb[r * 65 + c] = fb2[(size_t)(b * L_ + l0 + r) * C_ + h * 64 + c];
    }
    __syncthreads();
    int r = tid >> 2, q4 = tid & 3;
    float fs = fscale[0];
    float aq[16], ak[16];
    #pragma unroll
    for (int d = 0; d < 16; d++) { aq[d] = wqb[q4 * 16 + d]; ak[d] = wkb[q4 * 16 + d]; }
    for (int e = 0; e < 64; e++) {
        float fe = sfb[r * 65 + e];
        #pragma unroll
        for (int d = 0; d < 16; d++) {
            aq[d] += fe * swq[e * 64 + q4 * 16 + d];
            ak[d] += fe * swk[e * 64 + q4 * 16 + d];
        }
    }
    size_t base = (size_t)bh * L_ + l0 + r;
    __half* qrow = Qe + base * 128;
    __half* krow = Ke + base * 128;
    size_t qkvrow = (size_t)(b * L_ + l0 + r) * (3 * C_);
    int lpos = permh(r);        // within-16 interleave of key index
    #pragma unroll
    for (int dd = 0; dd < 16; dd += 2) {
        int d = q4 * 16 + dd;
        // bias-extension dims [64..127]
        *(__half2*)(qrow + permh(64 + d)) = __floats2half2_rn(fs * aq[dd], fs * aq[dd + 1]);
        *(__half2*)(krow + permh(64 + d)) = __floats2half2_rn(ak[dd], ak[dd + 1]);
        // base dims [0..63]
        float q0 = SCALE_ * qkv[qkvrow + h * 64 + d];
        float q1 = SCALE_ * qkv[qkvrow + h * 64 + d + 1];
        *(__half2*)(qrow + permh(d)) = __floats2half2_rn(q0, q1);
        float k0v = qkv[qkvrow + C_ + h * 64 + d];
        float k1v = qkv[qkvrow + C_ + h * 64 + d + 1];
        *(__half2*)(krow + permh(d)) = __floats2half2_rn(k0v, k1v);
        // V staged transposed: vstage[d][permh(l)]
        vstage[d * 72 + lpos]       = __float2half_rn(qkv[qkvrow + 2 * C_ + h * 64 + d]);
        vstage[(d + 1) * 72 + lpos] = __float2half_rn(qkv[qkvrow + 2 * C_ + h * 64 + d + 1]);
    }
    __syncthreads();
    // coalesced write of Vt rows: [bh][d][L], 64 rows x 64 halves = 8 uint4/row
    for (int i = tid; i < 64 * 8; i += 256) {
        int d = i >> 3, ch = i & 7;
        *(uint4*)(Vt + ((size_t)bh * 64 + d) * L_ + l0 + ch * 8) =
            *(const uint4*)(vstage + d * 72 + ch * 8);
    }
}

// ---------- fp16 tensor-core flash attention, D_qk=128, D_v=64 --------------
#define QSTRH 136
#define KSTRH 136
#define VSTRH 72
#define PSTRH 72
#define ATTN_SMEM ((128*QSTRH + 2*64*KSTRH + 2*64*VSTRH) * 2)   // 88064 B
__global__ __launch_bounds__(256, 1) void attn_tc(
    const __half* __restrict__ Qe, const __half* __restrict__ Ke,
    const __half* __restrict__ Vt, __half* __restrict__ O) {
    extern __shared__ __half smh[];
    __half* Qs  = smh;                     // 128 x 136; reused as Ps (128 x 72)
    __half* Ks0 = smh + 128 * QSTRH;       // 2 x 64 x 136
    __half* Vs0 = Ks0 + 2 * 64 * KSTRH;    // 2 x 64 x 72
    int qt = blockIdx.x, bh = blockIdx.y;
    int tid = threadIdx.x, lane = tid & 31, wid = tid >> 5;
    int r = lane >> 2, g = lane & 3;
    const __half* Qp = Qe + ((size_t)bh * L_ + qt * 128) * 128;
    const __half* Kp = Ke + (size_t)bh * L_ * 128;
    const __half* Vp = Vt + (size_t)bh * 64 * L_;

    auto issueKV = [&](int t) {
        __half* Ks = Ks0 + (t & 1) * 64 * KSTRH;
        __half* Vs = Vs0 + (t & 1) * 64 * VSTRH;
        const __half* Kt = Kp + (size_t)t * 64 * 128;
        #pragma unroll
        for (int it = 0; it < 4; it++) {            // K: 64 x 128 halves
            int i = tid + it * 256;
            int rr = i >> 4, cc = (i & 15) * 8;
            cp16(Ks + rr * KSTRH + cc, Kt + rr * 128 + cc);
        }
        #pragma unroll
        for (int it = 0; it < 2; it++) {            // V: 64 d-rows x 64 halves
            int i = tid + it * 256;
            int rr = i >> 3, cc = (i & 7) * 8;
            cp16(Vs + rr * VSTRH + cc, Vp + (size_t)rr * L_ + t * 64 + cc);
        }
        asm volatile("cp.async.commit_group;");
    };
    issueKV(0);

    for (int i = tid; i < 2048; i += 256) {          // Q: 128 x 128 halves
        int rr = i >> 4, cc = (i & 15) * 8;
        *(uint4*)(Qs + rr * QSTRH + cc) = *(const uint4*)(Qp + rr * 128 + cc);
    }
    __syncthreads();
    uint2 qlo[8], qhi[8];
    int qrb = (wid * 16 + r) * QSTRH;
    #pragma unroll
    for (int ks = 0; ks < 8; ks++) {
        qlo[ks] = *(const uint2*)(Qs + qrb + ks * 16 + 4 * g);
        qhi[ks] = *(const uint2*)(Qs + qrb + 8 * QSTRH + ks * 16 + 4 * g);
    }
    __syncthreads();
    __half* Ps = Qs;

    float o[8][4];
    #pragma unroll
    for (int ni = 0; ni < 8; ni++)
        #pragma unroll
        for (int q = 0; q < 4; q++) o[ni][q] = 0.f;
    float m0 = -1e30f, m1 = -1e30f, l0 = 0.f, l1 = 0.f;

    for (int t = 0; t < L_ / 64; t++) {
        if (t + 1 < L_ / 64) {
            issueKV(t + 1);
            asm volatile("cp.async.wait_group 1;");
        } else {
            asm volatile("cp.async.wait_group 0;");
        }
        __syncthreads();
        const __half* Ks = Ks0 + (t & 1) * 64 * KSTRH;
        const __half* Vs = Vs0 + (t & 1) * 64 * VSTRH;

        // S = Q @ K^T  (8 k16 steps over D_qk=128)
        float c[8][4];
        #pragma unroll
        for (int ni = 0; ni < 8; ni++)
            #pragma unroll
            for (int q = 0; q < 4; q++) c[ni][q] = 0.f;
        #pragma unroll
        for (int ks = 0; ks < 8; ks++) {
            uint2 bb[8];
            #pragma unroll
            for (int ni = 0; ni < 8; ni++)
                bb[ni] = *(const uint2*)(Ks + (ni * 8 + r) * KSTRH + ks * 16 + 4 * g);
            #pragma unroll
            for (int ni = 0; ni < 8; ni++)
                MMA_F16(c[ni][0], c[ni][1], c[ni][2], c[ni][3],
                        qlo[ks].x, qhi[ks].x, qlo[ks].y, qhi[ks].y,
                        bb[ni].x, bb[ni].y);
        }

        // online softmax (rows wid*16+r and +8; quad lanes share a row)
        float mx0 = -1e30f, mx1 = -1e30f;
        #pragma unroll
        for (int ni = 0; ni < 8; ni++) {
            mx0 = fmaxf(mx0, fmaxf(c[ni][0], c[ni][1]));
            mx1 = fmaxf(mx1, fmaxf(c[ni][2], c[ni][3]));
        }
        #pragma unroll
        for (int ofs = 1; ofs <= 2; ofs <<= 1) {
            mx0 = fmaxf(mx0, __shfl_xor_sync(0xffffffffu, mx0, ofs));
            mx1 = fmaxf(mx1, __shfl_xor_sync(0xffffffffu, mx1, ofs));
        }
        float mn0 = fmaxf(m0, mx0), mn1 = fmaxf(m1, mx1);
        float al0 = __expf(m0 - mn0), al1 = __expf(m1 - mn1);
        float rs0 = 0.f, rs1 = 0.f;
        int prow0 = (wid * 16 + r) * PSTRH;
        int prow1 = prow0 + 8 * PSTRH;
        #pragma unroll
        for (int ni = 0; ni < 8; ni++) {
            float p0 = __expf(c[ni][0] - mn0);
            float p1 = __expf(c[ni][1] - mn0);
            float p2 = __expf(c[ni][2] - mn1);
            float p3 = __expf(c[ni][3] - mn1);
            rs0 += p0 + p1; rs1 += p2 + p3;
            int pc = permh(ni * 8 + 2 * g);
            *(__half2*)(Ps + prow0 + pc) = __floats2half2_rn(p0, p1);
            *(__half2*)(Ps + prow1 + pc) = __floats2half2_rn(p2, p3);
        }
        #pragma unroll
        for (int ofs = 1; ofs <= 2; ofs <<= 1) {
            rs0 += __shfl_xor_sync(0xffffffffu, rs0, ofs);
            rs1 += __shfl_xor_sync(0xffffffffu, rs1, ofs);
        }
        l0 = l0 * al0 + rs0; l1 = l1 * al1 + rs1;
        m0 = mn0; m1 = mn1;
        #pragma unroll
        for (int ni = 0; ni < 8; ni++) {
            o[ni][0] *= al0; o[ni][1] *= al0;
            o[ni][2] *= al1; o[ni][3] *= al1;
        }
        __syncwarp();

        // O += P @ V  (4 k16 steps over 64 keys; V rows = output dims)
        #pragma unroll
        for (int ks = 0; ks < 4; ks++) {
            uint2 alo = *(const uint2*)(Ps + prow0 + ks * 16 + 4 * g);
            uint2 ahi = *(const uint2*)(Ps + prow1 + ks * 16 + 4 * g);
            uint2 bb[8];
            #pragma unroll
            for (int ni = 0; ni < 8; ni++)
                bb[ni] = *(const uint2*)(Vs + (ni * 8 + r) * VSTRH + ks * 16 + 4 * g);
            #pragma unroll
            for (int ni = 0; ni < 8; ni++)
                MMA_F16(o[ni][0], o[ni][1], o[ni][2], o[ni][3],
                        alo.x, ahi.x, alo.y, ahi.y, bb[ni].x, bb[ni].y);
        }
        __syncthreads();
    }

    // write O: half, permh layout (A of out-proj fp16 GEMM)
    int b = bh >> 4, h = bh & 15;
    int l0row = qt * 128 + wid * 16 + r;
    float inv0 = 1.0f / l0, inv1 = 1.0f / l1;
    __half* orow0 = O + (size_t)(b * L_ + l0row) * C_;
    __half* orow1 = O + (size_t)(b * L_ + l0row + 8) * C_;
    #pragma unroll
    for (int ni = 0; ni < 8; ni++) {
        int col = h * 64 + ni * 8 + 2 * g;
        *(__half2*)(orow0 + permh(col)) = __floats2half2_rn(o[ni][0] * inv0, o[ni][1] * inv0);
        *(__half2*)(orow1 + permh(col)) = __floats2half2_rn(o[ni][2] * inv1, o[ni][3] * inv1);
    }
}

// ---------------------------------------------------------------------------
extern "C" void kernel_launch(void* const* d_in, const int* in_sizes, int n_in,
                              void* d_out, int out_size) {
    const float* x        = (const float*)d_in[0];
    const float* freqd    = (const float*)d_in[1];
    const float* qkv_w    = (const float*)d_in[2];
    const float* qkv_b    = (const float*)d_in[3];
    const float* fp_w1    = (const float*)d_in[4];
    const float* fp_b1    = (const float*)d_in[5];
    const float* fp_ln_g  = (const float*)d_in[6];
    const float* fp_ln_b  = (const float*)d_in[7];
    const float* fp_w2    = (const float*)d_in[8];
    const float* fp_b2    = (const float*)d_in[9];
    const float* wq_w     = (const float*)d_in[10];
    const float* wq_b     = (const float*)d_in[11];
    const float* wk_w     = (const float*)d_in[12];
    const float* wk_b     = (const float*)d_in[13];
    const float* out_w    = (const float*)d_in[14];
    const float* out_b    = (const float*)d_in[15];
    const float* n1_g     = (const float*)d_in[16];
    const float* n1_b     = (const float*)d_in[17];
    const float* n2_g     = (const float*)d_in[18];
    const float* n2_b     = (const float*)d_in[19];
    const float* mlp_w1   = (const float*)d_in[20];
    const float* mlp_b1   = (const float*)d_in[21];
    const float* mlp_w2   = (const float*)d_in[22];
    const float* mlp_b2   = (const float*)d_in[23];
    const float* fscale   = (const float*)d_in[24];
    float* out = (float*)d_out;

    __half *p_xn, *p_fbg, *p_Qe, *p_Ke, *p_Vt, *p_O, *p_xn2, *p_h;
    float *p_qkv, *p_fb2, *p_xmid;
    __half *pw_qkv, *pw_fp2, *pw_out, *pw_m1, *pw_m2;
    cudaGetSymbolAddress((void**)&p_xn,   g_xn);
    cudaGetSymbolAddress((void**)&p_qkv,  g_qkv);
    cudaGetSymbolAddress((void**)&p_fbg,  g_fbg);
    cudaGetSymbolAddress((void**)&p_fb2,  g_fb2);
    cudaGetSymbolAddress((void**)&p_Qe,   g_Qe);
    cudaGetSymbolAddress((void**)&p_Ke,   g_Ke);
    cudaGetSymbolAddress((void**)&p_Vt,   g_Vt);
    cudaGetSymbolAddress((void**)&p_O,    g_O);
    cudaGetSymbolAddress((void**)&p_xmid, g_xmid);
    cudaGetSymbolAddress((void**)&p_xn2,  g_xn2);
    cudaGetSymbolAddress((void**)&p_h,    g_h);
    cudaGetSymbolAddress((void**)&pw_qkv, g_wt_qkv);
    cudaGetSymbolAddress((void**)&pw_fp2, g_wt_fp2);
    cudaGetSymbolAddress((void**)&pw_out, g_wt_out);
    cudaGetSymbolAddress((void**)&pw_m1,  g_wt_m1);
    cudaGetSymbolAddress((void**)&pw_m2,  g_wt_m2);

    cudaFuncSetAttribute(gemm_tc, cudaFuncAttributeMaxDynamicSharedMemorySize, GEMM_SMEM);
    cudaFuncSetAttribute(attn_tc, cudaFuncAttributeMaxDynamicSharedMemorySize, ATTN_SMEM);
    cudaFuncSetAttribute(build_ext_kernel, cudaFuncAttributeMaxDynamicSharedMemorySize, BE_SMEM);

    // 1. merged weight transpose + fp16 convert (+permh)
    wtrans_all<<<T_TOT, dim3(32, 8)>>>(qkv_w, fp_w2, out_w, mlp_w1, mlp_w2,
                                       pw_qkv, pw_fp2, pw_out, pw_m1, pw_m2);
    // 2. LN1 -> half permh
    ln_kernel<<<ROWS, 256>>>(x, n1_g, n1_b, p_xn);
    // 3. freq rank-1 + LN + GELU -> half permh
    fb1_kernel<<<ROWS, 256>>>(freqd, fp_w1, fp_b1, fp_ln_g, fp_ln_b, p_fbg);
    // 4. fb @ fp_w2 -> fp32  (PROFILED)
    gemm_tc<<<dim3(C_ / 128, ROWS / 128), 256, GEMM_SMEM>>>(
        p_fbg, pw_fp2, fp_b2, nullptr, p_fb2, nullptr, ROWS, C_, C_, 0);
    // 5. QKV projection -> fp32
    gemm_tc<<<dim3(3 * C_ / 128, ROWS / 128), 256, GEMM_SMEM>>>(
        p_xn, pw_qkv, qkv_b, nullptr, p_qkv, nullptr, ROWS, 3 * C_, C_, 0);
    // 6. build extended Q/K (half permh) + V-transposed (half)
    build_ext_kernel<<<dim3(L_ / 64, B_ * H_), 256, BE_SMEM>>>(
        p_qkv, p_fb2, wq_w, wq_b, wk_w, wk_b, fscale, p_Qe, p_Ke, p_Vt);
    // 7. fp16 tensor-core flash attention -> O half permh
    attn_tc<<<dim3(L_ / 128, B_ * H_), 256, ATTN_SMEM>>>(p_Qe, p_Ke, p_Vt, p_O);
    // 8. out projection + residual(x) -> xmid fp32
    gemm_tc<<<dim3(C_ / 128, ROWS / 128), 256, GEMM_SMEM>>>(
        p_O, pw_out, out_b, x, p_xmid, nullptr, ROWS, C_, C_, 0);
    // 9. LN2 -> half permh
    ln_kernel<<<ROWS, 256>>>(p_xmid, n2_g, n2_b, p_xn2);
    // 10. MLP up + GELU -> h half permh
    gemm_tc<<<dim3(FF_ / 128, ROWS / 128), 256, GEMM_SMEM>>>(
        p_xn2, pw_m1, mlp_b1, nullptr, nullptr, p_h, ROWS, FF_, C_, 1);
    // 11. MLP down + residual(xmid) -> final output fp32
    gemm_tc<<<dim3(C_ / 128, ROWS / 128), 256, GEMM_SMEM>>>(
        p_h, pw_m2, mlp_b2, p_xmid, out, nullptr, ROWS, C_, FF_, 0);
}

// round 13
// speedup vs baseline: 1.7382x; 1.7382x over previous
#include <cuda_runtime.h>
#include <cuda_fp16.h>
#include <cstdint>
#include <math.h>

#define B_  2
#define L_  2048
#define C_  1024
#define H_  16
#define HD_ 64
#define FF_ 4096
#define ROWS (B_*L_)          // 4096
#define SCALE_ 0.125f         // 64^-0.5
#define EPS_ 1e-5f

// ---------------- scratch (allocation-free rule: __device__ globals) --------
__device__ __half g_xn  [ROWS*C_];        // LN1 out, half, permh layout
__device__ float  g_qkv [ROWS*3*C_];      // qkv proj out, fp32
__device__ __half g_fbg [ROWS*C_];        // fb1 out, half, permh
__device__ float  g_fb2 [ROWS*C_];        // fb @ fp_w2, fp32
__device__ __half g_Qe  [B_*H_*L_*128];   // half, permh layout
__device__ __half g_Ke  [B_*H_*L_*128];   // half, permh layout
__device__ __half g_Vt  [B_*H_*HD_*L_];   // half, [bh][64][L], permh on l%16
__device__ __half g_O   [ROWS*C_];        // attn out, half, permh
__device__ float  g_xmid[ROWS*C_];        // fp32
__device__ __half g_xn2 [ROWS*C_];        // LN2 out, half, permh
__device__ __half g_h   [ROWS*FF_];       // mlp hidden, half, permh
// transposed half weights [N][K], permh on k
__device__ __half g_wt_qkv[3*C_*C_];
__device__ __half g_wt_fp2[C_*C_];
__device__ __half g_wt_out[C_*C_];
__device__ __half g_wt_m1 [FF_*C_];
__device__ __half g_wt_m2 [C_*FF_];

__device__ __forceinline__ float gelu_exact(float v) {
    return 0.5f * v * (1.0f + erff(v * 0.70710678118654752f));
}
__device__ __forceinline__ void cp16(void* smem_dst, const void* gmem_src) {
    unsigned int s = (unsigned int)__cvta_generic_to_shared(smem_dst);
    asm volatile("cp.async.cg.shared.global [%0], [%1], 16;" :: "r"(s), "l"(gmem_src));
}
// fp16 layout interleave within 16: (2g,2g+1,2g+8,2g+9) contiguous at 4g
__device__ __forceinline__ int permh(int k) {
    return (k & ~15) | (k & 1) | (((k >> 3) & 1) << 1) | (((k >> 1) & 3) << 2);
}
#define MMA_F16(c0,c1,c2,c3,a0,a1,a2,a3,b0,b1) \
    asm volatile("mma.sync.aligned.m16n8k16.row.col.f32.f16.f16.f32 " \
        "{%0,%1,%2,%3}, {%4,%5,%6,%7}, {%8,%9}, {%0,%1,%2,%3};" \
        : "+f"(c0), "+f"(c1), "+f"(c2), "+f"(c3) \
        : "r"(a0), "r"(a1), "r"(a2), "r"(a3), "r"(b0), "r"(b1))

// ------- merged weight transpose + fp16 convert (+permh on k) ---------------
#define T_QKV (32*96)
#define T_FP2 (32*32)
#define T_OUT (32*32)
#define T_M1  (32*128)
#define T_M2  (128*32)
#define T_TOT (T_QKV + T_FP2 + T_OUT + T_M1 + T_M2)
__global__ void wtrans_all(const float* __restrict__ qkv_w, const float* __restrict__ fp_w2,
                           const float* __restrict__ out_w, const float* __restrict__ m1_w,
                           const float* __restrict__ m2_w,
                           __half* __restrict__ t_qkv, __half* __restrict__ t_fp2,
                           __half* __restrict__ t_out, __half* __restrict__ t_m1,
                           __half* __restrict__ t_m2) {
    __shared__ float t[32][33];
    int bid = blockIdx.x;
    const float* W; __half* Wt; int K, N, tile;
    if (bid < T_QKV)                    { W = qkv_w; Wt = t_qkv; K = C_;  N = 3*C_; tile = bid; }
    else if ((bid -= T_QKV) < T_FP2)    { W = fp_w2; Wt = t_fp2; K = C_;  N = C_;   tile = bid; }
    else if ((bid -= T_FP2) < T_OUT)    { W = out_w; Wt = t_out; K = C_;  N = C_;   tile = bid; }
    else if ((bid -= T_OUT) < T_M1)     { W = m1_w;  Wt = t_m1;  K = C_;  N = FF_;  tile = bid; }
    else { bid -= T_M1;                   W = m2_w;  Wt = t_m2;  K = FF_; N = C_;   tile = bid; }
    int ntiles_n = N / 32;
    int k0 = (tile / ntiles_n) * 32;
    int n0 = (tile % ntiles_n) * 32;
    int tx = threadIdx.x, ty = threadIdx.y;
    #pragma unroll
    for (int j = 0; j < 4; j++) {
        int k = k0 + ty + j * 8;
        t[ty + j * 8][tx] = W[(size_t)k * N + n0 + tx];
    }
    __syncthreads();
    int kdst = permh(k0 + tx);
    #pragma unroll
    for (int j = 0; j < 4; j++) {
        int nn = n0 + ty + j * 8;
        Wt[(size_t)nn * K + kdst] = __float2half_rn(t[tx][ty + j * 8]);
    }
}

// ---------------- LayerNorm -> half, permh layout ---------------------------
__global__ void ln_kernel(const float* __restrict__ X, const float* __restrict__ g,
                          const float* __restrict__ b, __half* __restrict__ Y) {
    int row = blockIdx.x;
    int tid = threadIdx.x;
    const float4* xr = (const float4*)(X + (size_t)row * C_);
    float4 t = xr[tid];
    float s  = t.x + t.y + t.z + t.w;
    float sq = t.x*t.x + t.y*t.y + t.z*t.z + t.w*t.w;
    #pragma unroll
    for (int o = 16; o; o >>= 1) {
        s  += __shfl_xor_sync(0xffffffffu, s,  o);
        sq += __shfl_xor_sync(0xffffffffu, sq, o);
    }
    __shared__ float ws[8], wq[8];
    __shared__ float mean_s, rstd_s;
    int w = tid >> 5;
    if ((tid & 31) == 0) { ws[w] = s; wq[w] = sq; }
    __syncthreads();
    if (tid == 0) {
        float S = 0.f, Q = 0.f;
        #pragma unroll
        for (int i = 0; i < 8; i++) { S += ws[i]; Q += wq[i]; }
        float mean = S * (1.0f / C_);
        float var  = Q * (1.0f / C_) - mean * mean;
        mean_s = mean; rstd_s = rsqrtf(var + EPS_);
    }
    __syncthreads();
    float mean = mean_s, rstd = rstd_s;
    float4 gg = ((const float4*)g)[tid];
    float4 bb = ((const float4*)b)[tid];
    __half2 p0 = __floats2half2_rn((t.x - mean) * rstd * gg.x + bb.x,
                                   (t.y - mean) * rstd * gg.y + bb.y);
    __half2 p1 = __floats2half2_rn((t.z - mean) * rstd * gg.z + bb.z,
                                   (t.w - mean) * rstd * gg.w + bb.w);
    __half* yr = Y + (size_t)row * C_;
    int c0 = tid * 4;
    *(__half2*)(yr + permh(c0))     = p0;
    *(__half2*)(yr + permh(c0 + 2)) = p1;
}

// ------- freq path stage 1: rank-1 outer + LN + GELU -> half permh ----------
__global__ void fb1_kernel(const float* __restrict__ fd, const float* __restrict__ w1,
                           const float* __restrict__ b1, const float* __restrict__ g,
                           const float* __restrict__ bln, __half* __restrict__ Y) {
    int row = blockIdx.x;
    int tid = threadIdx.x;
    float f = fd[row];
    float4 w = ((const float4*)w1)[tid];
    float4 bb = ((const float4*)b1)[tid];
    float4 t;
    t.x = f * w.x + bb.x; t.y = f * w.y + bb.y;
    t.z = f * w.z + bb.z; t.w = f * w.w + bb.w;
    float s  = t.x + t.y + t.z + t.w;
    float sq = t.x*t.x + t.y*t.y + t.z*t.z + t.w*t.w;
    #pragma unroll
    for (int o = 16; o; o >>= 1) {
        s  += __shfl_xor_sync(0xffffffffu, s,  o);
        sq += __shfl_xor_sync(0xffffffffu, sq, o);
    }
    __shared__ float ws[8], wqs[8];
    __shared__ float mean_s, rstd_s;
    int w5 = tid >> 5;
    if ((tid & 31) == 0) { ws[w5] = s; wqs[w5] = sq; }
    __syncthreads();
    if (tid == 0) {
        float S = 0.f, Q = 0.f;
        #pragma unroll
        for (int i = 0; i < 8; i++) { S += ws[i]; Q += wqs[i]; }
        float mean = S * (1.0f / C_);
        float var  = Q * (1.0f / C_) - mean * mean;
        mean_s = mean; rstd_s = rsqrtf(var + EPS_);
    }
    __syncthreads();
    float mean = mean_s, rstd = rstd_s;
    float4 gg = ((const float4*)g)[tid];
    float4 bl = ((const float4*)bln)[tid];
    __half2 p0 = __floats2half2_rn(gelu_exact((t.x - mean) * rstd * gg.x + bl.x),
                                   gelu_exact((t.y - mean) * rstd * gg.y + bl.y));
    __half2 p1 = __floats2half2_rn(gelu_exact((t.z - mean) * rstd * gg.z + bl.z),
                                   gelu_exact((t.w - mean) * rstd * gg.w + bl.w));
    __half* yr = Y + (size_t)row * C_;
    int c0 = tid * 4;
    *(__half2*)(yr + permh(c0))     = p0;
    *(__half2*)(yr + permh(c0 + 2)) = p1;
}

// ---- fp16 TC GEMM: 128x128 CTA, 64x32 warp tiles, BK=32, 3-stage, occ2 -----
#define BK_ 32
#define HSTR 48
#define A_STH (128*HSTR)
#define B_STH (128*HSTR)
#define STGH  (A_STH + B_STH)
#define GEMM_SMEM (3*STGH*2)       // 73728 B

__global__ __launch_bounds__(256, 2) void gemm_tc(
    const __half* __restrict__ A, const __half* __restrict__ Bt,
    const float* __restrict__ bias, const float* __restrict__ R,
    float* __restrict__ Cf, __half* __restrict__ Ch,
    int M, int N, int K, int act) {
    extern __shared__ __half smh[];
    int tid = threadIdx.x;
    int lane = tid & 31, wid = tid >> 5;
    int wm = wid & 1, wn = wid >> 1;
    int m0 = blockIdx.y * 128, n0 = blockIdx.x * 128;

    float c[4][4][4];
    #pragma unroll
    for (int mi = 0; mi < 4; mi++)
        #pragma unroll
        for (int ni = 0; ni < 4; ni++)
            #pragma unroll
            for (int q = 0; q < 4; q++) c[mi][ni][q] = 0.f;

    int NT = K / BK_;
    auto issue = [&](int t) {
        __half* As = smh + (t % 3) * STGH;
        __half* Bs = As + A_STH;
        int k0 = t * BK_;
        #pragma unroll
        for (int it = 0; it < 2; it++) {
            int i = tid + it * 256;
            int row = i >> 2, off = (i & 3) * 8;
            cp16(As + row * HSTR + off, A + (size_t)(m0 + row) * K + k0 + off);
            cp16(Bs + row * HSTR + off, Bt + (size_t)(n0 + row) * K + k0 + off);
        }
        asm volatile("cp.async.commit_group;");
    };
    issue(0);
    issue(1);

    int r = lane >> 2, g = lane & 3;
    for (int t = 0; t < NT; t++) {
        if (t + 1 < NT) asm volatile("cp.async.wait_group 1;");
        else            asm volatile("cp.async.wait_group 0;");
        __syncthreads();
        if (t + 2 < NT) issue(t + 2);

        const __half* As = smh + (t % 3) * STGH;
        const __half* Bs = As + A_STH;
        #pragma unroll
        for (int ks = 0; ks < 2; ks++) {
            uint2 alo[4], ahi[4], bb[4];
            #pragma unroll
            for (int mi = 0; mi < 4; mi++) {
                alo[mi] = ((const uint2*)(As + (wm * 64 + mi * 16 + r) * HSTR))[ks * 4 + g];
                ahi[mi] = ((const uint2*)(As + (wm * 64 + mi * 16 + r + 8) * HSTR))[ks * 4 + g];
            }
            #pragma unroll
            for (int ni = 0; ni < 4; ni++)
                bb[ni] = ((const uint2*)(Bs + (wn * 32 + ni * 8 + r) * HSTR))[ks * 4 + g];
            #pragma unroll
            for (int mi = 0; mi < 4; mi++)
                #pragma unroll
                for (int ni = 0; ni < 4; ni++)
                    MMA_F16(c[mi][ni][0], c[mi][ni][1], c[mi][ni][2], c[mi][ni][3],
                            alo[mi].x, ahi[mi].x, alo[mi].y, ahi[mi].y,
                            bb[ni].x, bb[ni].y);
        }
    }

    #pragma unroll
    for (int mi = 0; mi < 4; mi++) {
        int row0 = m0 + wm * 64 + mi * 16 + r;
        #pragma unroll
        for (int ni = 0; ni < 4; ni++) {
            int col = n0 + wn * 32 + ni * 8 + g * 2;
            float b0 = bias[col], b1 = bias[col + 1];
            #pragma unroll
            for (int half_ = 0; half_ < 2; half_++) {
                int row = row0 + half_ * 8;
                float v0 = c[mi][ni][half_ * 2 + 0] + b0;
                float v1 = c[mi][ni][half_ * 2 + 1] + b1;
                if (act == 1) { v0 = gelu_exact(v0); v1 = gelu_exact(v1); }
                if (R) {
                    v0 += R[(size_t)row * N + col];
                    v1 += R[(size_t)row * N + col + 1];
                }
                if (Ch) {
                    *(__half2*)(Ch + (size_t)row * N + permh(col)) = __floats2half2_rn(v0, v1);
                } else {
                    *(float2*)(Cf + (size_t)row * N + col) = make_float2(v0, v1);
                }
            }
        }
    }
}

// ------- build extended Q/K (half permh) and V-transposed (half) ------------
#define BE_SMEM ((4096 + 4096 + 4160) * 4 + 64 * 72 * 2)   // 58624 B
__global__ void build_ext_kernel(const float* __restrict__ qkv, const float* __restrict__ fb2,
                                 const float* __restrict__ wqw, const float* __restrict__ wqb,
                                 const float* __restrict__ wkw, const float* __restrict__ wkb,
                                 const float* __restrict__ fscale,
                                 __half* __restrict__ Qe, __half* __restrict__ Ke,
                                 __half* __restrict__ Vt) {
    extern __shared__ char dynsm[];
    float* swq = (float*)dynsm;                  // 64*64
    float* swk = swq + 4096;                     // 64*64
    float* sfb = swk + 4096;                     // 64*65
    __half* vstage = (__half*)(sfb + 4160);      // 64 d x 72 (l permh'd)
    int bh = blockIdx.y;
    int lt = blockIdx.x;
    int b = bh >> 4, h = bh & 15;
    int l0 = lt * 64;
    int tid = threadIdx.x;
    for (int i = tid; i < 4096; i += 256) { swq[i] = wqw[i]; swk[i] = wkw[i]; }
    for (int i = tid; i < 4096; i += 256) {
        int r = i >> 6, c = i & 63;
        sfb[r * 65 + c] = fb2[(size_t)(b * L_ + l0 + r) * C_ + h * 64 + c];
    }
    __syncthreads();
    int r = tid >> 2, q4 = tid & 3;
    float fs = fscale[0];
    float aq[16], ak[16];
    #pragma unroll
    for (int d = 0; d < 16; d++) { aq[d] = wqb[q4 * 16 + d]; ak[d] = wkb[q4 * 16 + d]; }
    for (int e = 0; e < 64; e++) {
        float fe = sfb[r * 65 + e];
        #pragma unroll
        for (int d = 0; d < 16; d++) {
            aq[d] += fe * swq[e * 64 + q4 * 16 + d];
            ak[d] += fe * swk[e * 64 + q4 * 16 + d];
        }
    }
    size_t base = (size_t)bh * L_ + l0 + r;
    __half* qrow = Qe + base * 128;
    __half* krow = Ke + base * 128;
    size_t qkvrow = (size_t)(b * L_ + l0 + r) * (3 * C_);
    int lpos = permh(r);        // within-16 interleave of key index
    #pragma unroll
    for (int dd = 0; dd < 16; dd += 2) {
        int d = q4 * 16 + dd;
        // bias-extension dims [64..127]
        *(__half2*)(qrow + permh(64 + d)) = __floats2half2_rn(fs * aq[dd], fs * aq[dd + 1]);
        *(__half2*)(krow + permh(64 + d)) = __floats2half2_rn(ak[dd], ak[dd + 1]);
        // base dims [0..63]
        float q0 = SCALE_ * qkv[qkvrow + h * 64 + d];
        float q1 = SCALE_ * qkv[qkvrow + h * 64 + d + 1];
        *(__half2*)(qrow + permh(d)) = __floats2half2_rn(q0, q1);
        float k0v = qkv[qkvrow + C_ + h * 64 + d];
        float k1v = qkv[qkvrow + C_ + h * 64 + d + 1];
        *(__half2*)(krow + permh(d)) = __floats2half2_rn(k0v, k1v);
        // V staged transposed: vstage[d][permh(l)]
        vstage[d * 72 + lpos]       = __float2half_rn(qkv[qkvrow + 2 * C_ + h * 64 + d]);
        vstage[(d + 1) * 72 + lpos] = __float2half_rn(qkv[qkvrow + 2 * C_ + h * 64 + d + 1]);
    }
    __syncthreads();
    // coalesced write of Vt rows: [bh][d][L], 64 rows x 64 halves = 8 uint4/row
    for (int i = tid; i < 64 * 8; i += 256) {
        int d = i >> 3, ch = i & 7;
        *(uint4*)(Vt + ((size_t)bh * 64 + d) * L_ + l0 + ch * 8) =
            *(const uint4*)(vstage + d * 72 + ch * 8);
    }
}

// ---------- fp16 tensor-core flash attention, D_qk=128, D_v=64 --------------
// Strides chosen so LDS.64 fragment loads are bank-conflict-free:
// row stride mod 32 words must be 8 or 24 -> 144 halves (72 w) and 80 halves (40 w).
#define QSTRH 144
#define KSTRH 144
#define VSTRH 80
#define PSTRH 80
#define ATTN_SMEM ((128*QSTRH + 2*64*KSTRH + 2*64*VSTRH) * 2)   // 94208 B
__global__ __launch_bounds__(256, 1) void attn_tc(
    const __half* __restrict__ Qe, const __half* __restrict__ Ke,
    const __half* __restrict__ Vt, __half* __restrict__ O) {
    extern __shared__ __half smh[];
    __half* Qs  = smh;                     // 128 x 144; reused as Ps (128 x 80)
    __half* Ks0 = smh + 128 * QSTRH;       // 2 x 64 x 144
    __half* Vs0 = Ks0 + 2 * 64 * KSTRH;    // 2 x 64 x 80
    int qt = blockIdx.x, bh = blockIdx.y;
    int tid = threadIdx.x, lane = tid & 31, wid = tid >> 5;
    int r = lane >> 2, g = lane & 3;
    const __half* Qp = Qe + ((size_t)bh * L_ + qt * 128) * 128;
    const __half* Kp = Ke + (size_t)bh * L_ * 128;
    const __half* Vp = Vt + (size_t)bh * 64 * L_;

    auto issueKV = [&](int t) {
        __half* Ks = Ks0 + (t & 1) * 64 * KSTRH;
        __half* Vs = Vs0 + (t & 1) * 64 * VSTRH;
        const __half* Kt = Kp + (size_t)t * 64 * 128;
        #pragma unroll
        for (int it = 0; it < 4; it++) {            // K: 64 x 128 halves
            int i = tid + it * 256;
            int rr = i >> 4, cc = (i & 15) * 8;
            cp16(Ks + rr * KSTRH + cc, Kt + rr * 128 + cc);
        }
        #pragma unroll
        for (int it = 0; it < 2; it++) {            // V: 64 d-rows x 64 halves
            int i = tid + it * 256;
            int rr = i >> 3, cc = (i & 7) * 8;
            cp16(Vs + rr * VSTRH + cc, Vp + (size_t)rr * L_ + t * 64 + cc);
        }
        asm volatile("cp.async.commit_group;");
    };
    issueKV(0);

    for (int i = tid; i < 2048; i += 256) {          // Q: 128 x 128 halves
        int rr = i >> 4, cc = (i & 15) * 8;
        *(uint4*)(Qs + rr * QSTRH + cc) = *(const uint4*)(Qp + rr * 128 + cc);
    }
    __syncthreads();
    uint2 qlo[8], qhi[8];
    int qrb = (wid * 16 + r) * QSTRH;
    #pragma unroll
    for (int ks = 0; ks < 8; ks++) {
        qlo[ks] = *(const uint2*)(Qs + qrb + ks * 16 + 4 * g);
        qhi[ks] = *(const uint2*)(Qs + qrb + 8 * QSTRH + ks * 16 + 4 * g);
    }
    __syncthreads();
    __half* Ps = Qs;

    float o[8][4];
    #pragma unroll
    for (int ni = 0; ni < 8; ni++)
        #pragma unroll
        for (int q = 0; q < 4; q++) o[ni][q] = 0.f;
    float m0 = -1e30f, m1 = -1e30f, l0 = 0.f, l1 = 0.f;

    for (int t = 0; t < L_ / 64; t++) {
        if (t + 1 < L_ / 64) {
            issueKV(t + 1);
            asm volatile("cp.async.wait_group 1;");
        } else {
            asm volatile("cp.async.wait_group 0;");
        }
        __syncthreads();
        const __half* Ks = Ks0 + (t & 1) * 64 * KSTRH;
        const __half* Vs = Vs0 + (t & 1) * 64 * VSTRH;

        // S = Q @ K^T  (8 k16 steps over D_qk=128)
        float c[8][4];
        #pragma unroll
        for (int ni = 0; ni < 8; ni++)
            #pragma unroll
            for (int q = 0; q < 4; q++) c[ni][q] = 0.f;
        #pragma unroll
        for (int ks = 0; ks < 8; ks++) {
            uint2 bb[8];
            #pragma unroll
            for (int ni = 0; ni < 8; ni++)
                bb[ni] = *(const uint2*)(Ks + (ni * 8 + r) * KSTRH + ks * 16 + 4 * g);
            #pragma unroll
            for (int ni = 0; ni < 8; ni++)
                MMA_F16(c[ni][0], c[ni][1], c[ni][2], c[ni][3],
                        qlo[ks].x, qhi[ks].x, qlo[ks].y, qhi[ks].y,
                        bb[ni].x, bb[ni].y);
        }

        // online softmax (rows wid*16+r and +8; quad lanes share a row)
        float mx0 = -1e30f, mx1 = -1e30f;
        #pragma unroll
        for (int ni = 0; ni < 8; ni++) {
            mx0 = fmaxf(mx0, fmaxf(c[ni][0], c[ni][1]));
            mx1 = fmaxf(mx1, fmaxf(c[ni][2], c[ni][3]));
        }
        #pragma unroll
        for (int ofs = 1; ofs <= 2; ofs <<= 1) {
            mx0 = fmaxf(mx0, __shfl_xor_sync(0xffffffffu, mx0, ofs));
            mx1 = fmaxf(mx1, __shfl_xor_sync(0xffffffffu, mx1, ofs));
        }
        float mn0 = fmaxf(m0, mx0), mn1 = fmaxf(m1, mx1);
        float al0 = __expf(m0 - mn0), al1 = __expf(m1 - mn1);
        float rs0 = 0.f, rs1 = 0.f;
        int prow0 = (wid * 16 + r) * PSTRH;
        int prow1 = prow0 + 8 * PSTRH;
        #pragma unroll
        for (int ni = 0; ni < 8; ni++) {
            float p0 = __expf(c[ni][0] - mn0);
            float p1 = __expf(c[ni][1] - mn0);
            float p2 = __expf(c[ni][2] - mn1);
            float p3 = __expf(c[ni][3] - mn1);
            rs0 += p0 + p1; rs1 += p2 + p3;
            int pc = permh(ni * 8 + 2 * g);
            *(__half2*)(Ps + prow0 + pc) = __floats2half2_rn(p0, p1);
            *(__half2*)(Ps + prow1 + pc) = __floats2half2_rn(p2, p3);
        }
        #pragma unroll
        for (int ofs = 1; ofs <= 2; ofs <<= 1) {
            rs0 += __shfl_xor_sync(0xffffffffu, rs0, ofs);
            rs1 += __shfl_xor_sync(0xffffffffu, rs1, ofs);
        }
        l0 = l0 * al0 + rs0; l1 = l1 * al1 + rs1;
        m0 = mn0; m1 = mn1;
        #pragma unroll
        for (int ni = 0; ni < 8; ni++) {
            o[ni][0] *= al0; o[ni][1] *= al0;
            o[ni][2] *= al1; o[ni][3] *= al1;
        }
        __syncwarp();

        // O += P @ V  (4 k16 steps over 64 keys; V rows = output dims)
        #pragma unroll
        for (int ks = 0; ks < 4; ks++) {
            uint2 alo = *(const uint2*)(Ps + prow0 + ks * 16 + 4 * g);
            uint2 ahi = *(const uint2*)(Ps + prow1 + ks * 16 + 4 * g);
            uint2 bb[8];
            #pragma unroll
            for (int ni = 0; ni < 8; ni++)
                bb[ni] = *(const uint2*)(Vs + (ni * 8 + r) * VSTRH + ks * 16 + 4 * g);
            #pragma unroll
            for (int ni = 0; ni < 8; ni++)
                MMA_F16(o[ni][0], o[ni][1], o[ni][2], o[ni][3],
                        alo.x, ahi.x, alo.y, ahi.y, bb[ni].x, bb[ni].y);
        }
        __syncthreads();
    }

    // write O: half, permh layout (A of out-proj fp16 GEMM)
    int b = bh >> 4, h = bh & 15;
    int l0row = qt * 128 + wid * 16 + r;
    float inv0 = 1.0f / l0, inv1 = 1.0f / l1;
    __half* orow0 = O + (size_t)(b * L_ + l0row) * C_;
    __half* orow1 = O + (size_t)(b * L_ + l0row + 8) * C_;
    #pragma unroll
    for (int ni = 0; ni < 8; ni++) {
        int col = h * 64 + ni * 8 + 2 * g;
        *(__half2*)(orow0 + permh(col)) = __floats2half2_rn(o[ni][0] * inv0, o[ni][1] * inv0);
        *(__half2*)(orow1 + permh(col)) = __floats2half2_rn(o[ni][2] * inv1, o[ni][3] * inv1);
    }
}

// ---------------------------------------------------------------------------
extern "C" void kernel_launch(void* const* d_in, const int* in_sizes, int n_in,
                              void* d_out, int out_size) {
    const float* x        = (const float*)d_in[0];
    const float* freqd    = (const float*)d_in[1];
    const float* qkv_w    = (const float*)d_in[2];
    const float* qkv_b    = (const float*)d_in[3];
    const float* fp_w1    = (const float*)d_in[4];
    const float* fp_b1    = (const float*)d_in[5];
    const float* fp_ln_g  = (const float*)d_in[6];
    const float* fp_ln_b  = (const float*)d_in[7];
    const float* fp_w2    = (const float*)d_in[8];
    const float* fp_b2    = (const float*)d_in[9];
    const float* wq_w     = (const float*)d_in[10];
    const float* wq_b     = (const float*)d_in[11];
    const float* wk_w     = (const float*)d_in[12];
    const float* wk_b     = (const float*)d_in[13];
    const float* out_w    = (const float*)d_in[14];
    const float* out_b    = (const float*)d_in[15];
    const float* n1_g     = (const float*)d_in[16];
    const float* n1_b     = (const float*)d_in[17];
    const float* n2_g     = (const float*)d_in[18];
    const float* n2_b     = (const float*)d_in[19];
    const float* mlp_w1   = (const float*)d_in[20];
    const float* mlp_b1   = (const float*)d_in[21];
    const float* mlp_w2   = (const float*)d_in[22];
    const float* mlp_b2   = (const float*)d_in[23];
    const float* fscale   = (const float*)d_in[24];
    float* out = (float*)d_out;

    __half *p_xn, *p_fbg, *p_Qe, *p_Ke, *p_Vt, *p_O, *p_xn2, *p_h;
    float *p_qkv, *p_fb2, *p_xmid;
    __half *pw_qkv, *pw_fp2, *pw_out, *pw_m1, *pw_m2;
    cudaGetSymbolAddress((void**)&p_xn,   g_xn);
    cudaGetSymbolAddress((void**)&p_qkv,  g_qkv);
    cudaGetSymbolAddress((void**)&p_fbg,  g_fbg);
    cudaGetSymbolAddress((void**)&p_fb2,  g_fb2);
    cudaGetSymbolAddress((void**)&p_Qe,   g_Qe);
    cudaGetSymbolAddress((void**)&p_Ke,   g_Ke);
    cudaGetSymbolAddress((void**)&p_Vt,   g_Vt);
    cudaGetSymbolAddress((void**)&p_O,    g_O);
    cudaGetSymbolAddress((void**)&p_xmid, g_xmid);
    cudaGetSymbolAddress((void**)&p_xn2,  g_xn2);
    cudaGetSymbolAddress((void**)&p_h,    g_h);
    cudaGetSymbolAddress((void**)&pw_qkv, g_wt_qkv);
    cudaGetSymbolAddress((void**)&pw_fp2, g_wt_fp2);
    cudaGetSymbolAddress((void**)&pw_out, g_wt_out);
    cudaGetSymbolAddress((void**)&pw_m1,  g_wt_m1);
    cudaGetSymbolAddress((void**)&pw_m2,  g_wt_m2);

    cudaFuncSetAttribute(gemm_tc, cudaFuncAttributeMaxDynamicSharedMemorySize, GEMM_SMEM);
    cudaFuncSetAttribute(attn_tc, cudaFuncAttributeMaxDynamicSharedMemorySize, ATTN_SMEM);
    cudaFuncSetAttribute(build_ext_kernel, cudaFuncAttributeMaxDynamicSharedMemorySize, BE_SMEM);

    // 1. merged weight transpose + fp16 convert (+permh)
    wtrans_all<<<T_TOT, dim3(32, 8)>>>(qkv_w, fp_w2, out_w, mlp_w1, mlp_w2,
                                       pw_qkv, pw_fp2, pw_out, pw_m1, pw_m2);
    // 2. LN1 -> half permh
    ln_kernel<<<ROWS, 256>>>(x, n1_g, n1_b, p_xn);
    // 3. freq rank-1 + LN + GELU -> half permh
    fb1_kernel<<<ROWS, 256>>>(freqd, fp_w1, fp_b1, fp_ln_g, fp_ln_b, p_fbg);
    // 4. fb @ fp_w2 -> fp32  (PROFILED)
    gemm_tc<<<dim3(C_ / 128, ROWS / 128), 256, GEMM_SMEM>>>(
        p_fbg, pw_fp2, fp_b2, nullptr, p_fb2, nullptr, ROWS, C_, C_, 0);
    // 5. QKV projection -> fp32
    gemm_tc<<<dim3(3 * C_ / 128, ROWS / 128), 256, GEMM_SMEM>>>(
        p_xn, pw_qkv, qkv_b, nullptr, p_qkv, nullptr, ROWS, 3 * C_, C_, 0);
    // 6. build extended Q/K (half permh) + V-transposed (half)
    build_ext_kernel<<<dim3(L_ / 64, B_ * H_), 256, BE_SMEM>>>(
        p_qkv, p_fb2, wq_w, wq_b, wk_w, wk_b, fscale, p_Qe, p_Ke, p_Vt);
    // 7. fp16 tensor-core flash attention -> O half permh
    attn_tc<<<dim3(L_ / 128, B_ * H_), 256, ATTN_SMEM>>>(p_Qe, p_Ke, p_Vt, p_O);
    // 8. out projection + residual(x) -> xmid fp32
    gemm_tc<<<dim3(C_ / 128, ROWS / 128), 256, GEMM_SMEM>>>(
        p_O, pw_out, out_b, x, p_xmid, nullptr, ROWS, C_, C_, 0);
    // 9. LN2 -> half permh
    ln_kernel<<<ROWS, 256>>>(p_xmid, n2_g, n2_b, p_xn2);
    // 10. MLP up + GELU -> h half permh
    gemm_tc<<<dim3(FF_ / 128, ROWS / 128), 256, GEMM_SMEM>>>(
        p_xn2, pw_m1, mlp_b1, nullptr, nullptr, p_h, ROWS, FF_, C_, 1);
    // 11. MLP down + residual(xmid) -> final output fp32
    gemm_tc<<<dim3(C_ / 128, ROWS / 128), 256, GEMM_SMEM>>>(
        p_h, pw_m2, mlp_b2, p_xmid, out, nullptr, ROWS, C_, FF_, 0);
}

// round 14
// speedup vs baseline: 1.7533x; 1.0087x over previous
#include <cuda_runtime.h>
#include <cuda_fp16.h>
#include <cstdint>
#include <math.h>

#define B_  2
#define L_  2048
#define C_  1024
#define H_  16
#define HD_ 64
#define FF_ 4096
#define ROWS (B_*L_)          // 4096
#define SCALE_ 0.125f         // 64^-0.5
#define EPS_ 1e-5f

// ---------------- scratch (allocation-free rule: __device__ globals) --------
__device__ __half g_xn  [ROWS*C_];        // LN1 out, half, permh layout
__device__ float  g_qkv [ROWS*3*C_];      // qkv proj out, fp32
__device__ __half g_fbg [ROWS*C_];        // fb1 out, half, permh
__device__ float  g_fb2 [ROWS*C_];        // fb @ fp_w2, fp32
__device__ __half g_Qe  [B_*H_*L_*128];   // half, permh layout
__device__ __half g_Ke  [B_*H_*L_*128];   // half, permh layout
__device__ __half g_Vt  [B_*H_*HD_*L_];   // half, [bh][64][L], permh on l%16
__device__ __half g_O   [ROWS*C_];        // attn out, half, permh
__device__ float  g_xmid[ROWS*C_];        // fp32
__device__ __half g_xn2 [ROWS*C_];        // LN2 out, half, permh
__device__ __half g_h   [ROWS*FF_];       // mlp hidden, half, permh
// transposed half weights [N][K], permh on k
__device__ __half g_wt_qkv[3*C_*C_];
__device__ __half g_wt_fp2[C_*C_];
__device__ __half g_wt_out[C_*C_];
__device__ __half g_wt_m1 [FF_*C_];
__device__ __half g_wt_m2 [C_*FF_];

__device__ __forceinline__ float gelu_exact(float v) {
    return 0.5f * v * (1.0f + erff(v * 0.70710678118654752f));
}
__device__ __forceinline__ void cp16(void* smem_dst, const void* gmem_src) {
    unsigned int s = (unsigned int)__cvta_generic_to_shared(smem_dst);
    asm volatile("cp.async.cg.shared.global [%0], [%1], 16;" :: "r"(s), "l"(gmem_src));
}
// fp16 layout interleave within 16: (2g,2g+1,2g+8,2g+9) contiguous at 4g
__device__ __forceinline__ int permh(int k) {
    return (k & ~15) | (k & 1) | (((k >> 3) & 1) << 1) | (((k >> 1) & 3) << 2);
}
#define MMA_F16(c0,c1,c2,c3,a0,a1,a2,a3,b0,b1) \
    asm volatile("mma.sync.aligned.m16n8k16.row.col.f32.f16.f16.f32 " \
        "{%0,%1,%2,%3}, {%4,%5,%6,%7}, {%8,%9}, {%0,%1,%2,%3};" \
        : "+f"(c0), "+f"(c1), "+f"(c2), "+f"(c3) \
        : "r"(a0), "r"(a1), "r"(a2), "r"(a3), "r"(b0), "r"(b1))

// ------- merged weight transpose + fp16 convert (+permh on k) ---------------
#define T_QKV (32*96)
#define T_FP2 (32*32)
#define T_OUT (32*32)
#define T_M1  (32*128)
#define T_M2  (128*32)
#define T_TOT (T_QKV + T_FP2 + T_OUT + T_M1 + T_M2)
__global__ void wtrans_all(const float* __restrict__ qkv_w, const float* __restrict__ fp_w2,
                           const float* __restrict__ out_w, const float* __restrict__ m1_w,
                           const float* __restrict__ m2_w,
                           __half* __restrict__ t_qkv, __half* __restrict__ t_fp2,
                           __half* __restrict__ t_out, __half* __restrict__ t_m1,
                           __half* __restrict__ t_m2) {
    __shared__ float t[32][33];
    int bid = blockIdx.x;
    const float* W; __half* Wt; int K, N, tile;
    if (bid < T_QKV)                    { W = qkv_w; Wt = t_qkv; K = C_;  N = 3*C_; tile = bid; }
    else if ((bid -= T_QKV) < T_FP2)    { W = fp_w2; Wt = t_fp2; K = C_;  N = C_;   tile = bid; }
    else if ((bid -= T_FP2) < T_OUT)    { W = out_w; Wt = t_out; K = C_;  N = C_;   tile = bid; }
    else if ((bid -= T_OUT) < T_M1)     { W = m1_w;  Wt = t_m1;  K = C_;  N = FF_;  tile = bid; }
    else { bid -= T_M1;                   W = m2_w;  Wt = t_m2;  K = FF_; N = C_;   tile = bid; }
    int ntiles_n = N / 32;
    int k0 = (tile / ntiles_n) * 32;
    int n0 = (tile % ntiles_n) * 32;
    int tx = threadIdx.x, ty = threadIdx.y;
    #pragma unroll
    for (int j = 0; j < 4; j++) {
        int k = k0 + ty + j * 8;
        t[ty + j * 8][tx] = W[(size_t)k * N + n0 + tx];
    }
    __syncthreads();
    int kdst = permh(k0 + tx);
    #pragma unroll
    for (int j = 0; j < 4; j++) {
        int nn = n0 + ty + j * 8;
        Wt[(size_t)nn * K + kdst] = __float2half_rn(t[tx][ty + j * 8]);
    }
}

// ---------------- LayerNorm -> half, permh layout ---------------------------
__global__ void ln_kernel(const float* __restrict__ X, const float* __restrict__ g,
                          const float* __restrict__ b, __half* __restrict__ Y) {
    int row = blockIdx.x;
    int tid = threadIdx.x;
    const float4* xr = (const float4*)(X + (size_t)row * C_);
    float4 t = xr[tid];
    float s  = t.x + t.y + t.z + t.w;
    float sq = t.x*t.x + t.y*t.y + t.z*t.z + t.w*t.w;
    #pragma unroll
    for (int o = 16; o; o >>= 1) {
        s  += __shfl_xor_sync(0xffffffffu, s,  o);
        sq += __shfl_xor_sync(0xffffffffu, sq, o);
    }
    __shared__ float ws[8], wq[8];
    __shared__ float mean_s, rstd_s;
    int w = tid >> 5;
    if ((tid & 31) == 0) { ws[w] = s; wq[w] = sq; }
    __syncthreads();
    if (tid == 0) {
        float S = 0.f, Q = 0.f;
        #pragma unroll
        for (int i = 0; i < 8; i++) { S += ws[i]; Q += wq[i]; }
        float mean = S * (1.0f / C_);
        float var  = Q * (1.0f / C_) - mean * mean;
        mean_s = mean; rstd_s = rsqrtf(var + EPS_);
    }
    __syncthreads();
    float mean = mean_s, rstd = rstd_s;
    float4 gg = ((const float4*)g)[tid];
    float4 bb = ((const float4*)b)[tid];
    __half2 p0 = __floats2half2_rn((t.x - mean) * rstd * gg.x + bb.x,
                                   (t.y - mean) * rstd * gg.y + bb.y);
    __half2 p1 = __floats2half2_rn((t.z - mean) * rstd * gg.z + bb.z,
                                   (t.w - mean) * rstd * gg.w + bb.w);
    __half* yr = Y + (size_t)row * C_;
    int c0 = tid * 4;
    *(__half2*)(yr + permh(c0))     = p0;
    *(__half2*)(yr + permh(c0 + 2)) = p1;
}

// ------- freq path stage 1: rank-1 outer + LN + GELU -> half permh ----------
__global__ void fb1_kernel(const float* __restrict__ fd, const float* __restrict__ w1,
                           const float* __restrict__ b1, const float* __restrict__ g,
                           const float* __restrict__ bln, __half* __restrict__ Y) {
    int row = blockIdx.x;
    int tid = threadIdx.x;
    float f = fd[row];
    float4 w = ((const float4*)w1)[tid];
    float4 bb = ((const float4*)b1)[tid];
    float4 t;
    t.x = f * w.x + bb.x; t.y = f * w.y + bb.y;
    t.z = f * w.z + bb.z; t.w = f * w.w + bb.w;
    float s  = t.x + t.y + t.z + t.w;
    float sq = t.x*t.x + t.y*t.y + t.z*t.z + t.w*t.w;
    #pragma unroll
    for (int o = 16; o; o >>= 1) {
        s  += __shfl_xor_sync(0xffffffffu, s,  o);
        sq += __shfl_xor_sync(0xffffffffu, sq, o);
    }
    __shared__ float ws[8], wqs[8];
    __shared__ float mean_s, rstd_s;
    int w5 = tid >> 5;
    if ((tid & 31) == 0) { ws[w5] = s; wqs[w5] = sq; }
    __syncthreads();
    if (tid == 0) {
        float S = 0.f, Q = 0.f;
        #pragma unroll
        for (int i = 0; i < 8; i++) { S += ws[i]; Q += wqs[i]; }
        float mean = S * (1.0f / C_);
        float var  = Q * (1.0f / C_) - mean * mean;
        mean_s = mean; rstd_s = rsqrtf(var + EPS_);
    }
    __syncthreads();
    float mean = mean_s, rstd = rstd_s;
    float4 gg = ((const float4*)g)[tid];
    float4 bl = ((const float4*)bln)[tid];
    __half2 p0 = __floats2half2_rn(gelu_exact((t.x - mean) * rstd * gg.x + bl.x),
                                   gelu_exact((t.y - mean) * rstd * gg.y + bl.y));
    __half2 p1 = __floats2half2_rn(gelu_exact((t.z - mean) * rstd * gg.z + bl.z),
                                   gelu_exact((t.w - mean) * rstd * gg.w + bl.w));
    __half* yr = Y + (size_t)row * C_;
    int c0 = tid * 4;
    *(__half2*)(yr + permh(c0))     = p0;
    *(__half2*)(yr + permh(c0 + 2)) = p1;
}

// ---- fp16 TC GEMM: 128x128 CTA, 64x32 warp tiles, BK=64, 2-stage, occ2 -----
#define BK_ 64
#define HSTR 80                       // row stride (halves); 40 words mod 32 = 8 ✓
#define A_STH (128*HSTR)              // 10240 halves
#define B_STH (128*HSTR)
#define STGH  (A_STH + B_STH)         // 20480 halves = 40960 B
#define GEMM_SMEM (2*STGH*2)          // 81920 B

__global__ __launch_bounds__(256, 2) void gemm_tc(
    const __half* __restrict__ A, const __half* __restrict__ Bt,
    const float* __restrict__ bias, const float* __restrict__ R,
    float* __restrict__ Cf, __half* __restrict__ Ch,
    int M, int N, int K, int act) {
    extern __shared__ __half smh[];
    int tid = threadIdx.x;
    int lane = tid & 31, wid = tid >> 5;
    int wm = wid & 1, wn = wid >> 1;
    int m0 = blockIdx.y * 128, n0 = blockIdx.x * 128;

    float c[4][4][4];
    #pragma unroll
    for (int mi = 0; mi < 4; mi++)
        #pragma unroll
        for (int ni = 0; ni < 4; ni++)
            #pragma unroll
            for (int q = 0; q < 4; q++) c[mi][ni][q] = 0.f;

    int NT = K / BK_;
    auto issue = [&](int t) {
        __half* As = smh + (t & 1) * STGH;
        __half* Bs = As + A_STH;
        int k0 = t * BK_;
        #pragma unroll
        for (int it = 0; it < 4; it++) {        // 128 rows x 8 chunks of 8 halves
            int i = tid + it * 256;
            int row = i >> 3, off = (i & 7) * 8;
            cp16(As + row * HSTR + off, A + (size_t)(m0 + row) * K + k0 + off);
            cp16(Bs + row * HSTR + off, Bt + (size_t)(n0 + row) * K + k0 + off);
        }
        asm volatile("cp.async.commit_group;");
    };
    issue(0);

    int r = lane >> 2, g = lane & 3;
    for (int t = 0; t < NT; t++) {
        asm volatile("cp.async.wait_group 0;");   // tile t resident
        __syncthreads();                          // + all warps done with compute(t-1)
        if (t + 1 < NT) issue(t + 1);             // load next into the freed buffer

        const __half* As = smh + (t & 1) * STGH;
        const __half* Bs = As + A_STH;
        #pragma unroll
        for (int ks = 0; ks < 4; ks++) {          // four k16 steps per BK=64
            uint2 alo[4], ahi[4], bb[4];
            #pragma unroll
            for (int mi = 0; mi < 4; mi++) {
                alo[mi] = ((const uint2*)(As + (wm * 64 + mi * 16 + r) * HSTR))[ks * 4 + g];
                ahi[mi] = ((const uint2*)(As + (wm * 64 + mi * 16 + r + 8) * HSTR))[ks * 4 + g];
            }
            #pragma unroll
            for (int ni = 0; ni < 4; ni++)
                bb[ni] = ((const uint2*)(Bs + (wn * 32 + ni * 8 + r) * HSTR))[ks * 4 + g];
            #pragma unroll
            for (int mi = 0; mi < 4; mi++)
                #pragma unroll
                for (int ni = 0; ni < 4; ni++)
                    MMA_F16(c[mi][ni][0], c[mi][ni][1], c[mi][ni][2], c[mi][ni][3],
                            alo[mi].x, ahi[mi].x, alo[mi].y, ahi[mi].y,
                            bb[ni].x, bb[ni].y);
        }
    }

    #pragma unroll
    for (int mi = 0; mi < 4; mi++) {
        int row0 = m0 + wm * 64 + mi * 16 + r;
        #pragma unroll
        for (int ni = 0; ni < 4; ni++) {
            int col = n0 + wn * 32 + ni * 8 + g * 2;
            float b0 = bias[col], b1 = bias[col + 1];
            #pragma unroll
            for (int half_ = 0; half_ < 2; half_++) {
                int row = row0 + half_ * 8;
                float v0 = c[mi][ni][half_ * 2 + 0] + b0;
                float v1 = c[mi][ni][half_ * 2 + 1] + b1;
                if (act == 1) { v0 = gelu_exact(v0); v1 = gelu_exact(v1); }
                if (R) {
                    v0 += R[(size_t)row * N + col];
                    v1 += R[(size_t)row * N + col + 1];
                }
                if (Ch) {
                    *(__half2*)(Ch + (size_t)row * N + permh(col)) = __floats2half2_rn(v0, v1);
                } else {
                    *(float2*)(Cf + (size_t)row * N + col) = make_float2(v0, v1);
                }
            }
        }
    }
}

// ------- build extended Q/K (half permh) and V-transposed (half) ------------
#define BE_SMEM ((4096 + 4096 + 4160) * 4 + 64 * 72 * 2)   // 58624 B
__global__ void build_ext_kernel(const float* __restrict__ qkv, const float* __restrict__ fb2,
                                 const float* __restrict__ wqw, const float* __restrict__ wqb,
                                 const float* __restrict__ wkw, const float* __restrict__ wkb,
                                 const float* __restrict__ fscale,
                                 __half* __restrict__ Qe, __half* __restrict__ Ke,
                                 __half* __restrict__ Vt) {
    extern __shared__ char dynsm[];
    float* swq = (float*)dynsm;                  // 64*64
    float* swk = swq + 4096;                     // 64*64
    float* sfb = swk + 4096;                     // 64*65
    __half* vstage = (__half*)(sfb + 4160);      // 64 d x 72 (l permh'd)
    int bh = blockIdx.y;
    int lt = blockIdx.x;
    int b = bh >> 4, h = bh & 15;
    int l0 = lt * 64;
    int tid = threadIdx.x;
    for (int i = tid; i < 4096; i += 256) { swq[i] = wqw[i]; swk[i] = wkw[i]; }
    for (int i = tid; i < 4096; i += 256) {
        int r = i >> 6, c = i & 63;
        sfb[r * 65 + c] = fb2[(size_t)(b * L_ + l0 + r) * C_ + h * 64 + c];
    }
    __syncthreads();
    int r = tid >> 2, q4 = tid & 3;
    float fs = fscale[0];
    float aq[16], ak[16];
    #pragma unroll
    for (int d = 0; d < 16; d++) { aq[d] = wqb[q4 * 16 + d]; ak[d] = wkb[q4 * 16 + d]; }
    for (int e = 0; e < 64; e++) {
        float fe = sfb[r * 65 + e];
        #pragma unroll
        for (int d = 0; d < 16; d++) {
            aq[d] += fe * swq[e * 64 + q4 * 16 + d];
            ak[d] += fe * swk[e * 64 + q4 * 16 + d];
        }
    }
    size_t base = (size_t)bh * L_ + l0 + r;
    __half* qrow = Qe + base * 128;
    __half* krow = Ke + base * 128;
    size_t qkvrow = (size_t)(b * L_ + l0 + r) * (3 * C_);
    int lpos = permh(r);        // within-16 interleave of key index
    #pragma unroll
    for (int dd = 0; dd < 16; dd += 2) {
        int d = q4 * 16 + dd;
        // bias-extension dims [64..127]
        *(__half2*)(qrow + permh(64 + d)) = __floats2half2_rn(fs * aq[dd], fs * aq[dd + 1]);
        *(__half2*)(krow + permh(64 + d)) = __floats2half2_rn(ak[dd], ak[dd + 1]);
        // base dims [0..63]
        float q0 = SCALE_ * qkv[qkvrow + h * 64 + d];
        float q1 = SCALE_ * qkv[qkvrow + h * 64 + d + 1];
        *(__half2*)(qrow + permh(d)) = __floats2half2_rn(q0, q1);
        float k0v = qkv[qkvrow + C_ + h * 64 + d];
        float k1v = qkv[qkvrow + C_ + h * 64 + d + 1];
        *(__half2*)(krow + permh(d)) = __floats2half2_rn(k0v, k1v);
        // V staged transposed: vstage[d][permh(l)]
        vstage[d * 72 + lpos]       = __float2half_rn(qkv[qkvrow + 2 * C_ + h * 64 + d]);
        vstage[(d + 1) * 72 + lpos] = __float2half_rn(qkv[qkvrow + 2 * C_ + h * 64 + d + 1]);
    }
    __syncthreads();
    // coalesced write of Vt rows: [bh][d][L], 64 rows x 64 halves = 8 uint4/row
    for (int i = tid; i < 64 * 8; i += 256) {
        int d = i >> 3, ch = i & 7;
        *(uint4*)(Vt + ((size_t)bh * 64 + d) * L_ + l0 + ch * 8) =
            *(const uint4*)(vstage + d * 72 + ch * 8);
    }
}

// ---------- fp16 tensor-core flash attention, D_qk=128, D_v=64 --------------
// Strides chosen so LDS.64 fragment loads are bank-conflict-free:
// row stride mod 32 words must be 8 or 24 -> 144 halves (72 w) and 80 halves (40 w).
#define QSTRH 144
#define KSTRH 144
#define VSTRH 80
#define PSTRH 80
#define ATTN_SMEM ((128*QSTRH + 2*64*KSTRH + 2*64*VSTRH) * 2)   // 94208 B
__global__ __launch_bounds__(256, 1) void attn_tc(
    const __half* __restrict__ Qe, const __half* __restrict__ Ke,
    const __half* __restrict__ Vt, __half* __restrict__ O) {
    extern __shared__ __half smh[];
    __half* Qs  = smh;                     // 128 x 144; reused as Ps (128 x 80)
    __half* Ks0 = smh + 128 * QSTRH;       // 2 x 64 x 144
    __half* Vs0 = Ks0 + 2 * 64 * KSTRH;    // 2 x 64 x 80
    int qt = blockIdx.x, bh = blockIdx.y;
    int tid = threadIdx.x, lane = tid & 31, wid = tid >> 5;
    int r = lane >> 2, g = lane & 3;
    const __half* Qp = Qe + ((size_t)bh * L_ + qt * 128) * 128;
    const __half* Kp = Ke + (size_t)bh * L_ * 128;
    const __half* Vp = Vt + (size_t)bh * 64 * L_;

    auto issueKV = [&](int t) {
        __half* Ks = Ks0 + (t & 1) * 64 * KSTRH;
        __half* Vs = Vs0 + (t & 1) * 64 * VSTRH;
        const __half* Kt = Kp + (size_t)t * 64 * 128;
        #pragma unroll
        for (int it = 0; it < 4; it++) {            // K: 64 x 128 halves
            int i = tid + it * 256;
            int rr = i >> 4, cc = (i & 15) * 8;
            cp16(Ks + rr * KSTRH + cc, Kt + rr * 128 + cc);
        }
        #pragma unroll
        for (int it = 0; it < 2; it++) {            // V: 64 d-rows x 64 halves
            int i = tid + it * 256;
            int rr = i >> 3, cc = (i & 7) * 8;
            cp16(Vs + rr * VSTRH + cc, Vp + (size_t)rr * L_ + t * 64 + cc);
        }
        asm volatile("cp.async.commit_group;");
    };
    issueKV(0);

    for (int i = tid; i < 2048; i += 256) {          // Q: 128 x 128 halves
        int rr = i >> 4, cc = (i & 15) * 8;
        *(uint4*)(Qs + rr * QSTRH + cc) = *(const uint4*)(Qp + rr * 128 + cc);
    }
    __syncthreads();
    uint2 qlo[8], qhi[8];
    int qrb = (wid * 16 + r) * QSTRH;
    #pragma unroll
    for (int ks = 0; ks < 8; ks++) {
        qlo[ks] = *(const uint2*)(Qs + qrb + ks * 16 + 4 * g);
        qhi[ks] = *(const uint2*)(Qs + qrb + 8 * QSTRH + ks * 16 + 4 * g);
    }
    __syncthreads();
    __half* Ps = Qs;

    float o[8][4];
    #pragma unroll
    for (int ni = 0; ni < 8; ni++)
        #pragma unroll
        for (int q = 0; q < 4; q++) o[ni][q] = 0.f;
    float m0 = -1e30f, m1 = -1e30f, l0 = 0.f, l1 = 0.f;

    for (int t = 0; t < L_ / 64; t++) {
        if (t + 1 < L_ / 64) {
            issueKV(t + 1);
            asm volatile("cp.async.wait_group 1;");
        } else {
            asm volatile("cp.async.wait_group 0;");
        }
        __syncthreads();
        const __half* Ks = Ks0 + (t & 1) * 64 * KSTRH;
        const __half* Vs = Vs0 + (t & 1) * 64 * VSTRH;

        // S = Q @ K^T  (8 k16 steps over D_qk=128)
        float c[8][4];
        #pragma unroll
        for (int ni = 0; ni < 8; ni++)
            #pragma unroll
            for (int q = 0; q < 4; q++) c[ni][q] = 0.f;
        #pragma unroll
        for (int ks = 0; ks < 8; ks++) {
            uint2 bb[8];
            #pragma unroll
            for (int ni = 0; ni < 8; ni++)
                bb[ni] = *(const uint2*)(Ks + (ni * 8 + r) * KSTRH + ks * 16 + 4 * g);
            #pragma unroll
            for (int ni = 0; ni < 8; ni++)
                MMA_F16(c[ni][0], c[ni][1], c[ni][2], c[ni][3],
                        qlo[ks].x, qhi[ks].x, qlo[ks].y, qhi[ks].y,
                        bb[ni].x, bb[ni].y);
        }

        // online softmax (rows wid*16+r and +8; quad lanes share a row)
        float mx0 = -1e30f, mx1 = -1e30f;
        #pragma unroll
        for (int ni = 0; ni < 8; ni++) {
            mx0 = fmaxf(mx0, fmaxf(c[ni][0], c[ni][1]));
            mx1 = fmaxf(mx1, fmaxf(c[ni][2], c[ni][3]));
        }
        #pragma unroll
        for (int ofs = 1; ofs <= 2; ofs <<= 1) {
            mx0 = fmaxf(mx0, __shfl_xor_sync(0xffffffffu, mx0, ofs));
            mx1 = fmaxf(mx1, __shfl_xor_sync(0xffffffffu, mx1, ofs));
        }
        float mn0 = fmaxf(m0, mx0), mn1 = fmaxf(m1, mx1);
        float al0 = __expf(m0 - mn0), al1 = __expf(m1 - mn1);
        float rs0 = 0.f, rs1 = 0.f;
        int prow0 = (wid * 16 + r) * PSTRH;
        int prow1 = prow0 + 8 * PSTRH;
        #pragma unroll
        for (int ni = 0; ni < 8; ni++) {
            float p0 = __expf(c[ni][0] - mn0);
            float p1 = __expf(c[ni][1] - mn0);
            float p2 = __expf(c[ni][2] - mn1);
            float p3 = __expf(c[ni][3] - mn1);
            rs0 += p0 + p1; rs1 += p2 + p3;
            int pc = permh(ni * 8 + 2 * g);
            *(__half2*)(Ps + prow0 + pc) = __floats2half2_rn(p0, p1);
            *(__half2*)(Ps + prow1 + pc) = __floats2half2_rn(p2, p3);
        }
        #pragma unroll
        for (int ofs = 1; ofs <= 2; ofs <<= 1) {
            rs0 += __shfl_xor_sync(0xffffffffu, rs0, ofs);
            rs1 += __shfl_xor_sync(0xffffffffu, rs1, ofs);
        }
        l0 = l0 * al0 + rs0; l1 = l1 * al1 + rs1;
        m0 = mn0; m1 = mn1;
        #pragma unroll
        for (int ni = 0; ni < 8; ni++) {
            o[ni][0] *= al0; o[ni][1] *= al0;
            o[ni][2] *= al1; o[ni][3] *= al1;
        }
        __syncwarp();

        // O += P @ V  (4 k16 steps over 64 keys; V rows = output dims)
        #pragma unroll
        for (int ks = 0; ks < 4; ks++) {
            uint2 alo = *(const uint2*)(Ps + prow0 + ks * 16 + 4 * g);
            uint2 ahi = *(const uint2*)(Ps + prow1 + ks * 16 + 4 * g);
            uint2 bb[8];
            #pragma unroll
            for (int ni = 0; ni < 8; ni++)
                bb[ni] = *(const uint2*)(Vs + (ni * 8 + r) * VSTRH + ks * 16 + 4 * g);
            #pragma unroll
            for (int ni = 0; ni < 8; ni++)
                MMA_F16(o[ni][0], o[ni][1], o[ni][2], o[ni][3],
                        alo.x, ahi.x, alo.y, ahi.y, bb[ni].x, bb[ni].y);
        }
        __syncthreads();
    }

    // write O: half, permh layout (A of out-proj fp16 GEMM)
    int b = bh >> 4, h = bh & 15;
    int l0row = qt * 128 + wid * 16 + r;
    float inv0 = 1.0f / l0, inv1 = 1.0f / l1;
    __half* orow0 = O + (size_t)(b * L_ + l0row) * C_;
    __half* orow1 = O + (size_t)(b * L_ + l0row + 8) * C_;
    #pragma unroll
    for (int ni = 0; ni < 8; ni++) {
        int col = h * 64 + ni * 8 + 2 * g;
        *(__half2*)(orow0 + permh(col)) = __floats2half2_rn(o[ni][0] * inv0, o[ni][1] * inv0);
        *(__half2*)(orow1 + permh(col)) = __floats2half2_rn(o[ni][2] * inv1, o[ni][3] * inv1);
    }
}

// ---------------------------------------------------------------------------
extern "C" void kernel_launch(void* const* d_in, const int* in_sizes, int n_in,
                              void* d_out, int out_size) {
    const float* x        = (const float*)d_in[0];
    const float* freqd    = (const float*)d_in[1];
    const float* qkv_w    = (const float*)d_in[2];
    const float* qkv_b    = (const float*)d_in[3];
    const float* fp_w1    = (const float*)d_in[4];
    const float* fp_b1    = (const float*)d_in[5];
    const float* fp_ln_g  = (const float*)d_in[6];
    const float* fp_ln_b  = (const float*)d_in[7];
    const float* fp_w2    = (const float*)d_in[8];
    const float* fp_b2    = (const float*)d_in[9];
    const float* wq_w     = (const float*)d_in[10];
    const float* wq_b     = (const float*)d_in[11];
    const float* wk_w     = (const float*)d_in[12];
    const float* wk_b     = (const float*)d_in[13];
    const float* out_w    = (const float*)d_in[14];
    const float* out_b    = (const float*)d_in[15];
    const float* n1_g     = (const float*)d_in[16];
    const float* n1_b     = (const float*)d_in[17];
    const float* n2_g     = (const float*)d_in[18];
    const float* n2_b     = (const float*)d_in[19];
    const float* mlp_w1   = (const float*)d_in[20];
    const float* mlp_b1   = (const float*)d_in[21];
    const float* mlp_w2   = (const float*)d_in[22];
    const float* mlp_b2   = (const float*)d_in[23];
    const float* fscale   = (const float*)d_in[24];
    float* out = (float*)d_out;

    __half *p_xn, *p_fbg, *p_Qe, *p_Ke, *p_Vt, *p_O, *p_xn2, *p_h;
    float *p_qkv, *p_fb2, *p_xmid;
    __half *pw_qkv, *pw_fp2, *pw_out, *pw_m1, *pw_m2;
    cudaGetSymbolAddress((void**)&p_xn,   g_xn);
    cudaGetSymbolAddress((void**)&p_qkv,  g_qkv);
    cudaGetSymbolAddress((void**)&p_fbg,  g_fbg);
    cudaGetSymbolAddress((void**)&p_fb2,  g_fb2);
    cudaGetSymbolAddress((void**)&p_Qe,   g_Qe);
    cudaGetSymbolAddress((void**)&p_Ke,   g_Ke);
    cudaGetSymbolAddress((void**)&p_Vt,   g_Vt);
    cudaGetSymbolAddress((void**)&p_O,    g_O);
    cudaGetSymbolAddress((void**)&p_xmid, g_xmid);
    cudaGetSymbolAddress((void**)&p_xn2,  g_xn2);
    cudaGetSymbolAddress((void**)&p_h,    g_h);
    cudaGetSymbolAddress((void**)&pw_qkv, g_wt_qkv);
    cudaGetSymbolAddress((void**)&pw_fp2, g_wt_fp2);
    cudaGetSymbolAddress((void**)&pw_out, g_wt_out);
    cudaGetSymbolAddress((void**)&pw_m1,  g_wt_m1);
    cudaGetSymbolAddress((void**)&pw_m2,  g_wt_m2);

    cudaFuncSetAttribute(gemm_tc, cudaFuncAttributeMaxDynamicSharedMemorySize, GEMM_SMEM);
    cudaFuncSetAttribute(attn_tc, cudaFuncAttributeMaxDynamicSharedMemorySize, ATTN_SMEM);
    cudaFuncSetAttribute(build_ext_kernel, cudaFuncAttributeMaxDynamicSharedMemorySize, BE_SMEM);

    // 1. merged weight transpose + fp16 convert (+permh)
    wtrans_all<<<T_TOT, dim3(32, 8)>>>(qkv_w, fp_w2, out_w, mlp_w1, mlp_w2,
                                       pw_qkv, pw_fp2, pw_out, pw_m1, pw_m2);
    // 2. LN1 -> half permh
    ln_kernel<<<ROWS, 256>>>(x, n1_g, n1_b, p_xn);
    // 3. freq rank-1 + LN + GELU -> half permh
    fb1_kernel<<<ROWS, 256>>>(freqd, fp_w1, fp_b1, fp_ln_g, fp_ln_b, p_fbg);
    // 4. fb @ fp_w2 -> fp32  (PROFILED)
    gemm_tc<<<dim3(C_ / 128, ROWS / 128), 256, GEMM_SMEM>>>(
        p_fbg, pw_fp2, fp_b2, nullptr, p_fb2, nullptr, ROWS, C_, C_, 0);
    // 5. QKV projection -> fp32
    gemm_tc<<<dim3(3 * C_ / 128, ROWS / 128), 256, GEMM_SMEM>>>(
        p_xn, pw_qkv, qkv_b, nullptr, p_qkv, nullptr, ROWS, 3 * C_, C_, 0);
    // 6. build extended Q/K (half permh) + V-transposed (half)
    build_ext_kernel<<<dim3(L_ / 64, B_ * H_), 256, BE_SMEM>>>(
        p_qkv, p_fb2, wq_w, wq_b, wk_w, wk_b, fscale, p_Qe, p_Ke, p_Vt);
    // 7. fp16 tensor-core flash attention -> O half permh
    attn_tc<<<dim3(L_ / 128, B_ * H_), 256, ATTN_SMEM>>>(p_Qe, p_Ke, p_Vt, p_O);
    // 8. out projection + residual(x) -> xmid fp32
    gemm_tc<<<dim3(C_ / 128, ROWS / 128), 256, GEMM_SMEM>>>(
        p_O, pw_out, out_b, x, p_xmid, nullptr, ROWS, C_, C_, 0);
    // 9. LN2 -> half permh
    ln_kernel<<<ROWS, 256>>>(p_xmid, n2_g, n2_b, p_xn2);
    // 10. MLP up + GELU -> h half permh
    gemm_tc<<<dim3(FF_ / 128, ROWS / 128), 256, GEMM_SMEM>>>(
        p_xn2, pw_m1, mlp_b1, nullptr, nullptr, p_h, ROWS, FF_, C_, 1);
    // 11. MLP down + residual(xmid) -> final output fp32
    gemm_tc<<<dim3(C_ / 128, ROWS / 128), 256, GEMM_SMEM>>>(
        p_h, pw_m2, mlp_b2, p_xmid, out, nullptr, ROWS, C_, FF_, 0);
}

// round 15
// speedup vs baseline: 1.8737x; 1.0687x over previous
#include <cuda_runtime.h>
#include <cuda_fp16.h>
#include <cstdint>
#include <math.h>

#define B_  2
#define L_  2048
#define C_  1024
#define H_  16
#define HD_ 64
#define FF_ 4096
#define ROWS (B_*L_)          // 4096
#define SCALE_ 0.125f         // 64^-0.5
#define EPS_ 1e-5f

// ---------------- scratch (allocation-free rule: __device__ globals) --------
__device__ __half g_xn  [ROWS*C_];        // LN1 out, half, permh layout
__device__ __half g_fbg [ROWS*C_];        // fb1 out, half, permh
__device__ __half g_Qe  [B_*H_*L_*128];   // half, permh layout
__device__ __half g_Ke  [B_*H_*L_*128];   // half, permh layout
__device__ __half g_Vh  [B_*H_*L_*HD_];   // half, [bh][l][64] linear
__device__ __half g_Vt  [B_*H_*HD_*L_];   // half, [bh][64][L], permh on l%16
__device__ __half g_O   [ROWS*C_];        // attn out, half, permh
__device__ float  g_xmid[ROWS*C_];        // fp32
__device__ __half g_xn2 [ROWS*C_];        // LN2 out, half, permh
__device__ __half g_h   [ROWS*FF_];       // mlp hidden, half, permh
// transposed half weights [N][K], permh on k
__device__ __half g_wt_qkv[3*C_*C_];
__device__ __half g_wt_out[C_*C_];
__device__ __half g_wt_m1 [FF_*C_];
__device__ __half g_wt_m2 [C_*FF_];
// effective freq-bias projection weights (fp_w2 @ blockdiag(wq/wk)), [N][K] half permh
__device__ __half g_wt_qb[C_*C_];
__device__ __half g_wt_kb[C_*C_];
__device__ float  g_bq[C_];
__device__ float  g_bk[C_];

__device__ __forceinline__ float gelu_exact(float v) {
    return 0.5f * v * (1.0f + erff(v * 0.70710678118654752f));
}
__device__ __forceinline__ void cp16(void* smem_dst, const void* gmem_src) {
    unsigned int s = (unsigned int)__cvta_generic_to_shared(smem_dst);
    asm volatile("cp.async.cg.shared.global [%0], [%1], 16;" :: "r"(s), "l"(gmem_src));
}
// fp16 layout interleave within 16: (2g,2g+1,2g+8,2g+9) contiguous at 4g
__device__ __forceinline__ int permh(int k) {
    return (k & ~15) | (k & 1) | (((k >> 3) & 1) << 1) | (((k >> 1) & 3) << 2);
}
#define MMA_F16(c0,c1,c2,c3,a0,a1,a2,a3,b0,b1) \
    asm volatile("mma.sync.aligned.m16n8k16.row.col.f32.f16.f16.f32 " \
        "{%0,%1,%2,%3}, {%4,%5,%6,%7}, {%8,%9}, {%0,%1,%2,%3};" \
        : "+f"(c0), "+f"(c1), "+f"(c2), "+f"(c3) \
        : "r"(a0), "r"(a1), "r"(a2), "r"(a3), "r"(b0), "r"(b1))

// ------- merged weight transpose + fp16 convert (+permh on k) ---------------
#define T_QKV (32*96)
#define T_OUT (32*32)
#define T_M1  (32*128)
#define T_M2  (128*32)
#define T_TOT (T_QKV + T_OUT + T_M1 + T_M2)
__global__ void wtrans_all(const float* __restrict__ qkv_w, const float* __restrict__ out_w,
                           const float* __restrict__ m1_w, const float* __restrict__ m2_w,
                           __half* __restrict__ t_qkv, __half* __restrict__ t_out,
                           __half* __restrict__ t_m1, __half* __restrict__ t_m2) {
    __shared__ float t[32][33];
    int bid = blockIdx.x;
    const float* W; __half* Wt; int K, N, tile;
    if (bid < T_QKV)                    { W = qkv_w; Wt = t_qkv; K = C_;  N = 3*C_; tile = bid; }
    else if ((bid -= T_QKV) < T_OUT)    { W = out_w; Wt = t_out; K = C_;  N = C_;   tile = bid; }
    else if ((bid -= T_OUT) < T_M1)     { W = m1_w;  Wt = t_m1;  K = C_;  N = FF_;  tile = bid; }
    else { bid -= T_M1;                   W = m2_w;  Wt = t_m2;  K = FF_; N = C_;   tile = bid; }
    int ntiles_n = N / 32;
    int k0 = (tile / ntiles_n) * 32;
    int n0 = (tile % ntiles_n) * 32;
    int tx = threadIdx.x, ty = threadIdx.y;
    #pragma unroll
    for (int j = 0; j < 4; j++) {
        int k = k0 + ty + j * 8;
        t[ty + j * 8][tx] = W[(size_t)k * N + n0 + tx];
    }
    __syncthreads();
    int kdst = permh(k0 + tx);
    #pragma unroll
    for (int j = 0; j < 4; j++) {
        int nn = n0 + ty + j * 8;
        Wt[(size_t)nn * K + kdst] = __float2half_rn(t[tx][ty + j * 8]);
    }
}

// ------- effective freq weights: Wt_eff[h*64+d][e] = sum_e2 fp_w2[e][h*64+e2]*wq[e2][d]
__global__ void weff_kernel(const float* __restrict__ fp_w2, const float* __restrict__ wq_w,
                            const float* __restrict__ wk_w,
                            __half* __restrict__ Wtq, __half* __restrict__ Wtk) {
    __shared__ float sw[64 * 64];
    int et = blockIdx.x, h = blockIdx.y, which = blockIdx.z;
    const float* Wsm = which ? wk_w : wq_w;
    __half* Out = which ? Wtk : Wtq;
    int tid = threadIdx.x;
    for (int i = tid; i < 4096; i += 256) sw[i] = Wsm[i];
    __syncthreads();
    int d = tid & 63, eg = tid >> 6;
    for (int ee = 0; ee < 32; ee++) {
        int e = et * 128 + eg * 32 + ee;
        const float* w2row = fp_w2 + (size_t)e * C_ + h * 64;
        float acc = 0.f;
        #pragma unroll 8
        for (int e2 = 0; e2 < 64; e2++) acc += w2row[e2] * sw[e2 * 64 + d];
        Out[(size_t)(h * 64 + d) * C_ + permh(e)] = __float2half_rn(acc);
    }
}

// ------- effective biases: bq[h*64+d] = wq_b[d] + sum_e2 fp_b2[h*64+e2]*wq[e2][d]
__global__ void ebias_kernel(const float* __restrict__ fp_b2,
                             const float* __restrict__ wq_w, const float* __restrict__ wq_b,
                             const float* __restrict__ wk_w, const float* __restrict__ wk_b,
                             float* __restrict__ bq, float* __restrict__ bk) {
    int n = blockIdx.x * 256 + threadIdx.x;
    int h = n >> 6, d = n & 63;
    float aq = wq_b[d], ak = wk_b[d];
    for (int e2 = 0; e2 < 64; e2++) {
        float f = fp_b2[h * 64 + e2];
        aq += f * wq_w[e2 * 64 + d];
        ak += f * wk_w[e2 * 64 + d];
    }
    bq[n] = aq; bk[n] = ak;
}

// ---------------- LayerNorm -> half, permh layout ---------------------------
__global__ void ln_kernel(const float* __restrict__ X, const float* __restrict__ g,
                          const float* __restrict__ b, __half* __restrict__ Y) {
    int row = blockIdx.x;
    int tid = threadIdx.x;
    const float4* xr = (const float4*)(X + (size_t)row * C_);
    float4 t = xr[tid];
    float s  = t.x + t.y + t.z + t.w;
    float sq = t.x*t.x + t.y*t.y + t.z*t.z + t.w*t.w;
    #pragma unroll
    for (int o = 16; o; o >>= 1) {
        s  += __shfl_xor_sync(0xffffffffu, s,  o);
        sq += __shfl_xor_sync(0xffffffffu, sq, o);
    }
    __shared__ float ws[8], wq[8];
    __shared__ float mean_s, rstd_s;
    int w = tid >> 5;
    if ((tid & 31) == 0) { ws[w] = s; wq[w] = sq; }
    __syncthreads();
    if (tid == 0) {
        float S = 0.f, Q = 0.f;
        #pragma unroll
        for (int i = 0; i < 8; i++) { S += ws[i]; Q += wq[i]; }
        float mean = S * (1.0f / C_);
        float var  = Q * (1.0f / C_) - mean * mean;
        mean_s = mean; rstd_s = rsqrtf(var + EPS_);
    }
    __syncthreads();
    float mean = mean_s, rstd = rstd_s;
    float4 gg = ((const float4*)g)[tid];
    float4 bb = ((const float4*)b)[tid];
    __half2 p0 = __floats2half2_rn((t.x - mean) * rstd * gg.x + bb.x,
                                   (t.y - mean) * rstd * gg.y + bb.y);
    __half2 p1 = __floats2half2_rn((t.z - mean) * rstd * gg.z + bb.z,
                                   (t.w - mean) * rstd * gg.w + bb.w);
    __half* yr = Y + (size_t)row * C_;
    int c0 = tid * 4;
    *(__half2*)(yr + permh(c0))     = p0;
    *(__half2*)(yr + permh(c0 + 2)) = p1;
}

// ------- freq path stage 1: rank-1 outer + LN + GELU -> half permh ----------
__global__ void fb1_kernel(const float* __restrict__ fd, const float* __restrict__ w1,
                           const float* __restrict__ b1, const float* __restrict__ g,
                           const float* __restrict__ bln, __half* __restrict__ Y) {
    int row = blockIdx.x;
    int tid = threadIdx.x;
    float f = fd[row];
    float4 w = ((const float4*)w1)[tid];
    float4 bb = ((const float4*)b1)[tid];
    float4 t;
    t.x = f * w.x + bb.x; t.y = f * w.y + bb.y;
    t.z = f * w.z + bb.z; t.w = f * w.w + bb.w;
    float s  = t.x + t.y + t.z + t.w;
    float sq = t.x*t.x + t.y*t.y + t.z*t.z + t.w*t.w;
    #pragma unroll
    for (int o = 16; o; o >>= 1) {
        s  += __shfl_xor_sync(0xffffffffu, s,  o);
        sq += __shfl_xor_sync(0xffffffffu, sq, o);
    }
    __shared__ float ws[8], wqs[8];
    __shared__ float mean_s, rstd_s;
    int w5 = tid >> 5;
    if ((tid & 31) == 0) { ws[w5] = s; wqs[w5] = sq; }
    __syncthreads();
    if (tid == 0) {
        float S = 0.f, Q = 0.f;
        #pragma unroll
        for (int i = 0; i < 8; i++) { S += ws[i]; Q += wqs[i]; }
        float mean = S * (1.0f / C_);
        float var  = Q * (1.0f / C_) - mean * mean;
        mean_s = mean; rstd_s = rsqrtf(var + EPS_);
    }
    __syncthreads();
    float mean = mean_s, rstd = rstd_s;
    float4 gg = ((const float4*)g)[tid];
    float4 bl = ((const float4*)bln)[tid];
    __half2 p0 = __floats2half2_rn(gelu_exact((t.x - mean) * rstd * gg.x + bl.x),
                                   gelu_exact((t.y - mean) * rstd * gg.y + bl.y));
    __half2 p1 = __floats2half2_rn(gelu_exact((t.z - mean) * rstd * gg.z + bl.z),
                                   gelu_exact((t.w - mean) * rstd * gg.w + bl.w));
    __half* yr = Y + (size_t)row * C_;
    int c0 = tid * 4;
    *(__half2*)(yr + permh(c0))     = p0;
    *(__half2*)(yr + permh(c0 + 2)) = p1;
}

// ---- fp16 TC GEMM: 128x128 CTA, 64x32 warp tiles, BK=64, 2-stage, occ2 -----
// Epilogue modes: 0 = fp32 out (+R); 1 = half permh (+gelu opt);
//                 2 = QKV split (Ch=Qe *SCALE, Ch2=Ke, Ch3=Vh);
//                 3 = bias-ext into Ch at dims 64..127 (*fs if fsp).
#define BK_ 64
#define HSTR 80
#define A_STH (128*HSTR)
#define B_STH (128*HSTR)
#define STGH  (A_STH + B_STH)
#define GEMM_SMEM (2*STGH*2)          // 81920 B

__global__ __launch_bounds__(256, 2) void gemm_tc(
    const __half* __restrict__ A, const __half* __restrict__ Bt,
    const float* __restrict__ bias, const float* __restrict__ R,
    float* __restrict__ Cf, __half* __restrict__ Ch,
    __half* __restrict__ Ch2, __half* __restrict__ Ch3,
    const float* __restrict__ fsp,
    int M, int N, int K, int act, int mode) {
    extern __shared__ __half smh[];
    int tid = threadIdx.x;
    int lane = tid & 31, wid = tid >> 5;
    int wm = wid & 1, wn = wid >> 1;
    int m0 = blockIdx.y * 128, n0 = blockIdx.x * 128;

    float c[4][4][4];
    #pragma unroll
    for (int mi = 0; mi < 4; mi++)
        #pragma unroll
        for (int ni = 0; ni < 4; ni++)
            #pragma unroll
            for (int q = 0; q < 4; q++) c[mi][ni][q] = 0.f;

    int NT = K / BK_;
    auto issue = [&](int t) {
        __half* As = smh + (t & 1) * STGH;
        __half* Bs = As + A_STH;
        int k0 = t * BK_;
        #pragma unroll
        for (int it = 0; it < 4; it++) {
            int i = tid + it * 256;
            int row = i >> 3, off = (i & 7) * 8;
            cp16(As + row * HSTR + off, A + (size_t)(m0 + row) * K + k0 + off);
            cp16(Bs + row * HSTR + off, Bt + (size_t)(n0 + row) * K + k0 + off);
        }
        asm volatile("cp.async.commit_group;");
    };
    issue(0);

    int r = lane >> 2, g = lane & 3;
    for (int t = 0; t < NT; t++) {
        asm volatile("cp.async.wait_group 0;");
        __syncthreads();
        if (t + 1 < NT) issue(t + 1);

        const __half* As = smh + (t & 1) * STGH;
        const __half* Bs = As + A_STH;
        #pragma unroll
        for (int ks = 0; ks < 4; ks++) {
            uint2 alo[4], ahi[4], bb[4];
            #pragma unroll
            for (int mi = 0; mi < 4; mi++) {
                alo[mi] = ((const uint2*)(As + (wm * 64 + mi * 16 + r) * HSTR))[ks * 4 + g];
                ahi[mi] = ((const uint2*)(As + (wm * 64 + mi * 16 + r + 8) * HSTR))[ks * 4 + g];
            }
            #pragma unroll
            for (int ni = 0; ni < 4; ni++)
                bb[ni] = ((const uint2*)(Bs + (wn * 32 + ni * 8 + r) * HSTR))[ks * 4 + g];
            #pragma unroll
            for (int mi = 0; mi < 4; mi++)
                #pragma unroll
                for (int ni = 0; ni < 4; ni++)
                    MMA_F16(c[mi][ni][0], c[mi][ni][1], c[mi][ni][2], c[mi][ni][3],
                            alo[mi].x, ahi[mi].x, alo[mi].y, ahi[mi].y,
                            bb[ni].x, bb[ni].y);
        }
    }

    float fs = fsp ? fsp[0] : 1.0f;
    #pragma unroll
    for (int mi = 0; mi < 4; mi++) {
        int row0 = m0 + wm * 64 + mi * 16 + r;
        #pragma unroll
        for (int ni = 0; ni < 4; ni++) {
            int col = n0 + wn * 32 + ni * 8 + g * 2;
            float b0 = bias[col], b1 = bias[col + 1];
            #pragma unroll
            for (int half_ = 0; half_ < 2; half_++) {
                int row = row0 + half_ * 8;
                float v0 = c[mi][ni][half_ * 2 + 0] + b0;
                float v1 = c[mi][ni][half_ * 2 + 1] + b1;
                if (act == 1) { v0 = gelu_exact(v0); v1 = gelu_exact(v1); }
                if (mode == 0) {
                    if (R) {
                        v0 += R[(size_t)row * N + col];
                        v1 += R[(size_t)row * N + col + 1];
                    }
                    *(float2*)(Cf + (size_t)row * N + col) = make_float2(v0, v1);
                } else if (mode == 1) {
                    *(__half2*)(Ch + (size_t)row * N + permh(col)) = __floats2half2_rn(v0, v1);
                } else if (mode == 2) {
                    int part = col >> 10, cc = col & 1023, h = cc >> 6, d = cc & 63;
                    int bb_ = row >> 11, l = row & 2047;
                    size_t base = (size_t)(bb_ * 16 + h) * L_ + l;
                    if (part == 0)
                        *(__half2*)(Ch + base * 128 + permh(d)) =
                            __floats2half2_rn(SCALE_ * v0, SCALE_ * v1);
                    else if (part == 1)
                        *(__half2*)(Ch2 + base * 128 + permh(d)) = __floats2half2_rn(v0, v1);
                    else
                        *(__half2*)(Ch3 + base * 64 + d) = __floats2half2_rn(v0, v1);
                } else {   // mode 3: bias-ext dims 64..127, optional fs
                    int h = col >> 6, d = col & 63;
                    int bb_ = row >> 11, l = row & 2047;
                    size_t base = (size_t)(bb_ * 16 + h) * L_ + l;
                    *(__half2*)(Ch + base * 128 + permh(64 + d)) =
                        __floats2half2_rn(fs * v0, fs * v1);
                }
            }
        }
    }
}

// ------- V transpose stager: Vh [bh][l][64] -> Vt [bh][64][L] (l permh'd) ---
__global__ void vtrans_kernel(const __half* __restrict__ Vh, __half* __restrict__ Vt) {
    __shared__ __half vstage[64 * 72];
    int bh = blockIdx.y, l0 = blockIdx.x * 64, tid = threadIdx.x;
    int r = tid >> 2, q4 = tid & 3;
    const __half* src = Vh + ((size_t)bh * L_ + l0 + r) * 64 + q4 * 16;
    int lpos = permh(r);
    #pragma unroll
    for (int dd = 0; dd < 16; dd++)
        vstage[(q4 * 16 + dd) * 72 + lpos] = src[dd];
    __syncthreads();
    for (int i = tid; i < 64 * 8; i += 256) {
        int d = i >> 3, ch = i & 7;
        *(uint4*)(Vt + ((size_t)bh * 64 + d) * L_ + l0 + ch * 8) =
            *(const uint4*)(vstage + d * 72 + ch * 8);
    }
}

// ---------- fp16 tensor-core flash attention, D_qk=128, D_v=64 --------------
#define QSTRH 144
#define KSTRH 144
#define VSTRH 80
#define PSTRH 80
#define ATTN_SMEM ((128*QSTRH + 2*64*KSTRH + 2*64*VSTRH) * 2)   // 94208 B
__global__ __launch_bounds__(256, 1) void attn_tc(
    const __half* __restrict__ Qe, const __half* __restrict__ Ke,
    const __half* __restrict__ Vt, __half* __restrict__ O) {
    extern __shared__ __half smh[];
    __half* Qs  = smh;
    __half* Ks0 = smh + 128 * QSTRH;
    __half* Vs0 = Ks0 + 2 * 64 * KSTRH;
    int qt = blockIdx.x, bh = blockIdx.y;
    int tid = threadIdx.x, lane = tid & 31, wid = tid >> 5;
    int r = lane >> 2, g = lane & 3;
    const __half* Qp = Qe + ((size_t)bh * L_ + qt * 128) * 128;
    const __half* Kp = Ke + (size_t)bh * L_ * 128;
    const __half* Vp = Vt + (size_t)bh * 64 * L_;

    auto issueKV = [&](int t) {
        __half* Ks = Ks0 + (t & 1) * 64 * KSTRH;
        __half* Vs = Vs0 + (t & 1) * 64 * VSTRH;
        const __half* Kt = Kp + (size_t)t * 64 * 128;
        #pragma unroll
        for (int it = 0; it < 4; it++) {
            int i = tid + it * 256;
            int rr = i >> 4, cc = (i & 15) * 8;
            cp16(Ks + rr * KSTRH + cc, Kt + rr * 128 + cc);
        }
        #pragma unroll
        for (int it = 0; it < 2; it++) {
            int i = tid + it * 256;
            int rr = i >> 3, cc = (i & 7) * 8;
            cp16(Vs + rr * VSTRH + cc, Vp + (size_t)rr * L_ + t * 64 + cc);
        }
        asm volatile("cp.async.commit_group;");
    };
    issueKV(0);

    for (int i = tid; i < 2048; i += 256) {
        int rr = i >> 4, cc = (i & 15) * 8;
        *(uint4*)(Qs + rr * QSTRH + cc) = *(const uint4*)(Qp + rr * 128 + cc);
    }
    __syncthreads();
    uint2 qlo[8], qhi[8];
    int qrb = (wid * 16 + r) * QSTRH;
    #pragma unroll
    for (int ks = 0; ks < 8; ks++) {
        qlo[ks] = *(const uint2*)(Qs + qrb + ks * 16 + 4 * g);
        qhi[ks] = *(const uint2*)(Qs + qrb + 8 * QSTRH + ks * 16 + 4 * g);
    }
    __syncthreads();
    __half* Ps = Qs;

    float o[8][4];
    #pragma unroll
    for (int ni = 0; ni < 8; ni++)
        #pragma unroll
        for (int q = 0; q < 4; q++) o[ni][q] = 0.f;
    float m0 = -1e30f, m1 = -1e30f, l0 = 0.f, l1 = 0.f;

    for (int t = 0; t < L_ / 64; t++) {
        if (t + 1 < L_ / 64) {
            issueKV(t + 1);
            asm volatile("cp.async.wait_group 1;");
        } else {
            asm volatile("cp.async.wait_group 0;");
        }
        __syncthreads();
        const __half* Ks = Ks0 + (t & 1) * 64 * KSTRH;
        const __half* Vs = Vs0 + (t & 1) * 64 * VSTRH;

        float c[8][4];
        #pragma unroll
        for (int ni = 0; ni < 8; ni++)
            #pragma unroll
            for (int q = 0; q < 4; q++) c[ni][q] = 0.f;
        #pragma unroll
        for (int ks = 0; ks < 8; ks++) {
            uint2 bb[8];
            #pragma unroll
            for (int ni = 0; ni < 8; ni++)
                bb[ni] = *(const uint2*)(Ks + (ni * 8 + r) * KSTRH + ks * 16 + 4 * g);
            #pragma unroll
            for (int ni = 0; ni < 8; ni++)
                MMA_F16(c[ni][0], c[ni][1], c[ni][2], c[ni][3],
                        qlo[ks].x, qhi[ks].x, qlo[ks].y, qhi[ks].y,
                        bb[ni].x, bb[ni].y);
        }

        float mx0 = -1e30f, mx1 = -1e30f;
        #pragma unroll
        for (int ni = 0; ni < 8; ni++) {
            mx0 = fmaxf(mx0, fmaxf(c[ni][0], c[ni][1]));
            mx1 = fmaxf(mx1, fmaxf(c[ni][2], c[ni][3]));
        }
        #pragma unroll
        for (int ofs = 1; ofs <= 2; ofs <<= 1) {
            mx0 = fmaxf(mx0, __shfl_xor_sync(0xffffffffu, mx0, ofs));
            mx1 = fmaxf(mx1, __shfl_xor_sync(0xffffffffu, mx1, ofs));
        }
        float mn0 = fmaxf(m0, mx0), mn1 = fmaxf(m1, mx1);
        float al0 = __expf(m0 - mn0), al1 = __expf(m1 - mn1);
        float rs0 = 0.f, rs1 = 0.f;
        int prow0 = (wid * 16 + r) * PSTRH;
        int prow1 = prow0 + 8 * PSTRH;
        #pragma unroll
        for (int ni = 0; ni < 8; ni++) {
            float p0 = __expf(c[ni][0] - mn0);
            float p1 = __expf(c[ni][1] - mn0);
            float p2 = __expf(c[ni][2] - mn1);
            float p3 = __expf(c[ni][3] - mn1);
            rs0 += p0 + p1; rs1 += p2 + p3;
            int pc = permh(ni * 8 + 2 * g);
            *(__half2*)(Ps + prow0 + pc) = __floats2half2_rn(p0, p1);
            *(__half2*)(Ps + prow1 + pc) = __floats2half2_rn(p2, p3);
        }
        #pragma unroll
        for (int ofs = 1; ofs <= 2; ofs <<= 1) {
            rs0 += __shfl_xor_sync(0xffffffffu, rs0, ofs);
            rs1 += __shfl_xor_sync(0xffffffffu, rs1, ofs);
        }
        l0 = l0 * al0 + rs0; l1 = l1 * al1 + rs1;
        m0 = mn0; m1 = mn1;
        #pragma unroll
        for (int ni = 0; ni < 8; ni++) {
            o[ni][0] *= al0; o[ni][1] *= al0;
            o[ni][2] *= al1; o[ni][3] *= al1;
        }
        __syncwarp();

        #pragma unroll
        for (int ks = 0; ks < 4; ks++) {
            uint2 alo = *(const uint2*)(Ps + prow0 + ks * 16 + 4 * g);
            uint2 ahi = *(const uint2*)(Ps + prow1 + ks * 16 + 4 * g);
            uint2 bb[8];
            #pragma unroll
            for (int ni = 0; ni < 8; ni++)
                bb[ni] = *(const uint2*)(Vs + (ni * 8 + r) * VSTRH + ks * 16 + 4 * g);
            #pragma unroll
            for (int ni = 0; ni < 8; ni++)
                MMA_F16(o[ni][0], o[ni][1], o[ni][2], o[ni][3],
                        alo.x, ahi.x, alo.y, ahi.y, bb[ni].x, bb[ni].y);
        }
        __syncthreads();
    }

    int b = bh >> 4, h = bh & 15;
    int l0row = qt * 128 + wid * 16 + r;
    float inv0 = 1.0f / l0, inv1 = 1.0f / l1;
    __half* orow0 = O + (size_t)(b * L_ + l0row) * C_;
    __half* orow1 = O + (size_t)(b * L_ + l0row + 8) * C_;
    #pragma unroll
    for (int ni = 0; ni < 8; ni++) {
        int col = h * 64 + ni * 8 + 2 * g;
        *(__half2*)(orow0 + permh(col)) = __floats2half2_rn(o[ni][0] * inv0, o[ni][1] * inv0);
        *(__half2*)(orow1 + permh(col)) = __floats2half2_rn(o[ni][2] * inv1, o[ni][3] * inv1);
    }
}

// ---------------------------------------------------------------------------
extern "C" void kernel_launch(void* const* d_in, const int* in_sizes, int n_in,
                              void* d_out, int out_size) {
    const float* x        = (const float*)d_in[0];
    const float* freqd    = (const float*)d_in[1];
    const float* qkv_w    = (const float*)d_in[2];
    const float* qkv_b    = (const float*)d_in[3];
    const float* fp_w1    = (const float*)d_in[4];
    const float* fp_b1    = (const float*)d_in[5];
    const float* fp_ln_g  = (const float*)d_in[6];
    const float* fp_ln_b  = (const float*)d_in[7];
    const float* fp_w2    = (const float*)d_in[8];
    const float* fp_b2    = (const float*)d_in[9];
    const float* wq_w     = (const float*)d_in[10];
    const float* wq_b     = (const float*)d_in[11];
    const float* wk_w     = (const float*)d_in[12];
    const float* wk_b     = (const float*)d_in[13];
    const float* out_w    = (const float*)d_in[14];
    const float* out_b    = (const float*)d_in[15];
    const float* n1_g     = (const float*)d_in[16];
    const float* n1_b     = (const float*)d_in[17];
    const float* n2_g     = (const float*)d_in[18];
    const float* n2_b     = (const float*)d_in[19];
    const float* mlp_w1   = (const float*)d_in[20];
    const float* mlp_b1   = (const float*)d_in[21];
    const float* mlp_w2   = (const float*)d_in[22];
    const float* mlp_b2   = (const float*)d_in[23];
    const float* fscale   = (const float*)d_in[24];
    float* out = (float*)d_out;

    __half *p_xn, *p_fbg, *p_Qe, *p_Ke, *p_Vh, *p_Vt, *p_O, *p_xn2, *p_h;
    float *p_xmid, *p_bq, *p_bk;
    __half *pw_qkv, *pw_out, *pw_m1, *pw_m2, *pw_qb, *pw_kb;
    cudaGetSymbolAddress((void**)&p_xn,   g_xn);
    cudaGetSymbolAddress((void**)&p_fbg,  g_fbg);
    cudaGetSymbolAddress((void**)&p_Qe,   g_Qe);
    cudaGetSymbolAddress((void**)&p_Ke,   g_Ke);
    cudaGetSymbolAddress((void**)&p_Vh,   g_Vh);
    cudaGetSymbolAddress((void**)&p_Vt,   g_Vt);
    cudaGetSymbolAddress((void**)&p_O,    g_O);
    cudaGetSymbolAddress((void**)&p_xmid, g_xmid);
    cudaGetSymbolAddress((void**)&p_xn2,  g_xn2);
    cudaGetSymbolAddress((void**)&p_h,    g_h);
    cudaGetSymbolAddress((void**)&pw_qkv, g_wt_qkv);
    cudaGetSymbolAddress((void**)&pw_out, g_wt_out);
    cudaGetSymbolAddress((void**)&pw_m1,  g_wt_m1);
    cudaGetSymbolAddress((void**)&pw_m2,  g_wt_m2);
    cudaGetSymbolAddress((void**)&pw_qb,  g_wt_qb);
    cudaGetSymbolAddress((void**)&pw_kb,  g_wt_kb);
    cudaGetSymbolAddress((void**)&p_bq,   g_bq);
    cudaGetSymbolAddress((void**)&p_bk,   g_bk);

    cudaFuncSetAttribute(gemm_tc, cudaFuncAttributeMaxDynamicSharedMemorySize, GEMM_SMEM);
    cudaFuncSetAttribute(attn_tc, cudaFuncAttributeMaxDynamicSharedMemorySize, ATTN_SMEM);

    // 1. weight transpose + fp16 convert
    wtrans_all<<<T_TOT, dim3(32, 8)>>>(qkv_w, out_w, mlp_w1, mlp_w2,
                                       pw_qkv, pw_out, pw_m1, pw_m2);
    // 2. LN1 -> half permh
    ln_kernel<<<ROWS, 256>>>(x, n1_g, n1_b, p_xn);
    // 3. freq rank-1 + LN + GELU -> half permh
    fb1_kernel<<<ROWS, 256>>>(freqd, fp_w1, fp_b1, fp_ln_g, fp_ln_b, p_fbg);
    // 4. QKV projection, epilogue splits into Qe/Ke/Vh  (PROFILED)
    gemm_tc<<<dim3(3 * C_ / 128, ROWS / 128), 256, GEMM_SMEM>>>(
        p_xn, pw_qkv, qkv_b, nullptr, nullptr, p_Qe, p_Ke, p_Vh, nullptr,
        ROWS, 3 * C_, C_, 0, 2);
    // 5. effective freq-bias weights + biases (prepass)
    weff_kernel<<<dim3(8, 16, 2), 256>>>(fp_w2, wq_w, wk_w, pw_qb, pw_kb);
    ebias_kernel<<<4, 256>>>(fp_b2, wq_w, wq_b, wk_w, wk_b, p_bq, p_bk);
    // 6. qb = fbg @ Wq_eff -> Qe dims 64..127 (* fs)
    gemm_tc<<<dim3(C_ / 128, ROWS / 128), 256, GEMM_SMEM>>>(
        p_fbg, pw_qb, p_bq, nullptr, nullptr, p_Qe, nullptr, nullptr, fscale,
        ROWS, C_, C_, 0, 3);
    // 7. kb = fbg @ Wk_eff -> Ke dims 64..127
    gemm_tc<<<dim3(C_ / 128, ROWS / 128), 256, GEMM_SMEM>>>(
        p_fbg, pw_kb, p_bk, nullptr, nullptr, p_Ke, nullptr, nullptr, nullptr,
        ROWS, C_, C_, 0, 3);
    // 8. V transpose
    vtrans_kernel<<<dim3(L_ / 64, B_ * H_), 256>>>(p_Vh, p_Vt);
    // 9. fp16 tensor-core flash attention -> O half permh
    attn_tc<<<dim3(L_ / 128, B_ * H_), 256, ATTN_SMEM>>>(p_Qe, p_Ke, p_Vt, p_O);
    // 10. out projection + residual(x) -> xmid fp32
    gemm_tc<<<dim3(C_ / 128, ROWS / 128), 256, GEMM_SMEM>>>(
        p_O, pw_out, out_b, x, p_xmid, nullptr, nullptr, nullptr, nullptr,
        ROWS, C_, C_, 0, 0);
    // 11. LN2 -> half permh
    ln_kernel<<<ROWS, 256>>>(p_xmid, n2_g, n2_b, p_xn2);
    // 12. MLP up + GELU -> h half permh
    gemm_tc<<<dim3(FF_ / 128, ROWS / 128), 256, GEMM_SMEM>>>(
        p_xn2, pw_m1, mlp_b1, nullptr, nullptr, p_h, nullptr, nullptr, nullptr,
        ROWS, FF_, C_, 1, 1);
    // 13. MLP down + residual(xmid) -> final output fp32
    gemm_tc<<<dim3(C_ / 128, ROWS / 128), 256, GEMM_SMEM>>>(
        p_h, pw_m2, mlp_b2, p_xmid, out, nullptr, nullptr, nullptr, nullptr,
        ROWS, C_, FF_, 0, 0);
}

// round 16
// speedup vs baseline: 1.8745x; 1.0004x over previous
#include <cuda_runtime.h>
#include <cuda_fp16.h>
#include <cstdint>
#include <math.h>

#define B_  2
#define L_  2048
#define C_  1024
#define H_  16
#define HD_ 64
#define FF_ 4096
#define ROWS (B_*L_)          // 4096
#define SCALE_ 0.125f         // 64^-0.5
#define EPS_ 1e-5f

// ---------------- scratch (allocation-free rule: __device__ globals) --------
__device__ __half g_xn  [ROWS*C_];        // LN1 out, half, permh layout
__device__ __half g_fbg [ROWS*C_];        // fb1 out, half, permh
__device__ __half g_Qe  [B_*H_*L_*128];   // half, permh layout
__device__ __half g_Ke  [B_*H_*L_*128];   // half, permh layout
__device__ __half g_Vh  [B_*H_*L_*HD_];   // half, [bh][l][64] linear
__device__ __half g_Vt  [B_*H_*HD_*L_];   // half, [bh][64][L], permh on l%16
__device__ __half g_O   [ROWS*C_];        // attn out, half, permh
__device__ float  g_xmid[ROWS*C_];        // fp32
__device__ __half g_xn2 [ROWS*C_];        // LN2 out, half, permh
__device__ __half g_h   [ROWS*FF_];       // mlp hidden, half, permh
// transposed half weights [N][K], permh on k
__device__ __half g_wt_qkv[3*C_*C_];
__device__ __half g_wt_out[C_*C_];
__device__ __half g_wt_m1 [FF_*C_];
__device__ __half g_wt_m2 [C_*FF_];
// combined effective freq-bias weights [2C, C] (q rows then k rows), half permh
__device__ __half g_wt_qkb[2*C_*C_];
__device__ float  g_bqk[2*C_];

__device__ __forceinline__ float gelu_exact(float v) {
    return 0.5f * v * (1.0f + erff(v * 0.70710678118654752f));
}
__device__ __forceinline__ void cp16(void* smem_dst, const void* gmem_src) {
    unsigned int s = (unsigned int)__cvta_generic_to_shared(smem_dst);
    asm volatile("cp.async.cg.shared.global [%0], [%1], 16;" :: "r"(s), "l"(gmem_src));
}
// fp16 layout interleave within 16: (2g,2g+1,2g+8,2g+9) contiguous at 4g
__device__ __forceinline__ int permh(int k) {
    return (k & ~15) | (k & 1) | (((k >> 3) & 1) << 1) | (((k >> 1) & 3) << 2);
}
#define MMA_F16(c0,c1,c2,c3,a0,a1,a2,a3,b0,b1) \
    asm volatile("mma.sync.aligned.m16n8k16.row.col.f32.f16.f16.f32 " \
        "{%0,%1,%2,%3}, {%4,%5,%6,%7}, {%8,%9}, {%0,%1,%2,%3};" \
        : "+f"(c0), "+f"(c1), "+f"(c2), "+f"(c3) \
        : "r"(a0), "r"(a1), "r"(a2), "r"(a3), "r"(b0), "r"(b1))

// ------- merged weight transpose + fp16 convert (+permh on k) ---------------
#define T_QKV (32*96)
#define T_OUT (32*32)
#define T_M1  (32*128)
#define T_M2  (128*32)
#define T_TOT (T_QKV + T_OUT + T_M1 + T_M2)
__global__ void wtrans_all(const float* __restrict__ qkv_w, const float* __restrict__ out_w,
                           const float* __restrict__ m1_w, const float* __restrict__ m2_w,
                           __half* __restrict__ t_qkv, __half* __restrict__ t_out,
                           __half* __restrict__ t_m1, __half* __restrict__ t_m2) {
    __shared__ float t[32][33];
    int bid = blockIdx.x;
    const float* W; __half* Wt; int K, N, tile;
    if (bid < T_QKV)                    { W = qkv_w; Wt = t_qkv; K = C_;  N = 3*C_; tile = bid; }
    else if ((bid -= T_QKV) < T_OUT)    { W = out_w; Wt = t_out; K = C_;  N = C_;   tile = bid; }
    else if ((bid -= T_OUT) < T_M1)     { W = m1_w;  Wt = t_m1;  K = C_;  N = FF_;  tile = bid; }
    else { bid -= T_M1;                   W = m2_w;  Wt = t_m2;  K = FF_; N = C_;   tile = bid; }
    int ntiles_n = N / 32;
    int k0 = (tile / ntiles_n) * 32;
    int n0 = (tile % ntiles_n) * 32;
    int tx = threadIdx.x, ty = threadIdx.y;
    #pragma unroll
    for (int j = 0; j < 4; j++) {
        int k = k0 + ty + j * 8;
        t[ty + j * 8][tx] = W[(size_t)k * N + n0 + tx];
    }
    __syncthreads();
    int kdst = permh(k0 + tx);
    #pragma unroll
    for (int j = 0; j < 4; j++) {
        int nn = n0 + ty + j * 8;
        Wt[(size_t)nn * K + kdst] = __float2half_rn(t[tx][ty + j * 8]);
    }
}

// ------- effective freq weights (combined q|k) + effective biases -----------
// Wt_qkb[which*C + h*64+d][permh(e)] = sum_e2 fp_w2[e][h*64+e2] * w(q/k)[e2][d]
// bqk  [which*C + h*64+d] = w(q/k)_b[d] + sum_e2 fp_b2[h*64+e2] * w(q/k)[e2][d]
__global__ void weff_kernel(const float* __restrict__ fp_w2, const float* __restrict__ fp_b2,
                            const float* __restrict__ wq_w, const float* __restrict__ wq_b,
                            const float* __restrict__ wk_w, const float* __restrict__ wk_b,
                            __half* __restrict__ Wqkb, float* __restrict__ bqk) {
    __shared__ float sw[64 * 64];
    int et = blockIdx.x, h = blockIdx.y, which = blockIdx.z;
    const float* Wsm = which ? wk_w : wq_w;
    int tid = threadIdx.x;
    for (int i = tid; i < 4096; i += 256) sw[i] = Wsm[i];
    __syncthreads();
    int d = tid & 63, eg = tid >> 6;
    __half* Out = Wqkb + (size_t)which * C_ * C_;
    for (int ee = 0; ee < 32; ee++) {
        int e = et * 128 + eg * 32 + ee;
        const float* w2row = fp_w2 + (size_t)e * C_ + h * 64;
        float acc = 0.f;
        #pragma unroll 8
        for (int e2 = 0; e2 < 64; e2++) acc += w2row[e2] * sw[e2 * 64 + d];
        Out[(size_t)(h * 64 + d) * C_ + permh(e)] = __float2half_rn(acc);
    }
    // effective bias (first block column only; one thread per output dim)
    if (et == 0 && eg == 0) {
        const float* wb = which ? wk_b : wq_b;
        float a = wb[d];
        for (int e2 = 0; e2 < 64; e2++)
            a += fp_b2[h * 64 + e2] * sw[e2 * 64 + d];
        bqk[which * C_ + h * 64 + d] = a;
    }
}

// ---------------- LayerNorm -> half, permh layout ---------------------------
__global__ void ln_kernel(const float* __restrict__ X, const float* __restrict__ g,
                          const float* __restrict__ b, __half* __restrict__ Y) {
    int row = blockIdx.x;
    int tid = threadIdx.x;
    const float4* xr = (const float4*)(X + (size_t)row * C_);
    float4 t = xr[tid];
    float s  = t.x + t.y + t.z + t.w;
    float sq = t.x*t.x + t.y*t.y + t.z*t.z + t.w*t.w;
    #pragma unroll
    for (int o = 16; o; o >>= 1) {
        s  += __shfl_xor_sync(0xffffffffu, s,  o);
        sq += __shfl_xor_sync(0xffffffffu, sq, o);
    }
    __shared__ float ws[8], wq[8];
    __shared__ float mean_s, rstd_s;
    int w = tid >> 5;
    if ((tid & 31) == 0) { ws[w] = s; wq[w] = sq; }
    __syncthreads();
    if (tid == 0) {
        float S = 0.f, Q = 0.f;
        #pragma unroll
        for (int i = 0; i < 8; i++) { S += ws[i]; Q += wq[i]; }
        float mean = S * (1.0f / C_);
        float var  = Q * (1.0f / C_) - mean * mean;
        mean_s = mean; rstd_s = rsqrtf(var + EPS_);
    }
    __syncthreads();
    float mean = mean_s, rstd = rstd_s;
    float4 gg = ((const float4*)g)[tid];
    float4 bb = ((const float4*)b)[tid];
    __half2 p0 = __floats2half2_rn((t.x - mean) * rstd * gg.x + bb.x,
                                   (t.y - mean) * rstd * gg.y + bb.y);
    __half2 p1 = __floats2half2_rn((t.z - mean) * rstd * gg.z + bb.z,
                                   (t.w - mean) * rstd * gg.w + bb.w);
    __half* yr = Y + (size_t)row * C_;
    int c0 = tid * 4;
    *(__half2*)(yr + permh(c0))     = p0;
    *(__half2*)(yr + permh(c0 + 2)) = p1;
}

// ------- freq path stage 1: rank-1 outer + LN + GELU -> half permh ----------
__global__ void fb1_kernel(const float* __restrict__ fd, const float* __restrict__ w1,
                           const float* __restrict__ b1, const float* __restrict__ g,
                           const float* __restrict__ bln, __half* __restrict__ Y) {
    int row = blockIdx.x;
    int tid = threadIdx.x;
    float f = fd[row];
    float4 w = ((const float4*)w1)[tid];
    float4 bb = ((const float4*)b1)[tid];
    float4 t;
    t.x = f * w.x + bb.x; t.y = f * w.y + bb.y;
    t.z = f * w.z + bb.z; t.w = f * w.w + bb.w;
    float s  = t.x + t.y + t.z + t.w;
    float sq = t.x*t.x + t.y*t.y + t.z*t.z + t.w*t.w;
    #pragma unroll
    for (int o = 16; o; o >>= 1) {
        s  += __shfl_xor_sync(0xffffffffu, s,  o);
        sq += __shfl_xor_sync(0xffffffffu, sq, o);
    }
    __shared__ float ws[8], wqs[8];
    __shared__ float mean_s, rstd_s;
    int w5 = tid >> 5;
    if ((tid & 31) == 0) { ws[w5] = s; wqs[w5] = sq; }
    __syncthreads();
    if (tid == 0) {
        float S = 0.f, Q = 0.f;
        #pragma unroll
        for (int i = 0; i < 8; i++) { S += ws[i]; Q += wqs[i]; }
        float mean = S * (1.0f / C_);
        float var  = Q * (1.0f / C_) - mean * mean;
        mean_s = mean; rstd_s = rsqrtf(var + EPS_);
    }
    __syncthreads();
    float mean = mean_s, rstd = rstd_s;
    float4 gg = ((const float4*)g)[tid];
    float4 bl = ((const float4*)bln)[tid];
    __half2 p0 = __floats2half2_rn(gelu_exact((t.x - mean) * rstd * gg.x + bl.x),
                                   gelu_exact((t.y - mean) * rstd * gg.y + bl.y));
    __half2 p1 = __floats2half2_rn(gelu_exact((t.z - mean) * rstd * gg.z + bl.z),
                                   gelu_exact((t.w - mean) * rstd * gg.w + bl.w));
    __half* yr = Y + (size_t)row * C_;
    int c0 = tid * 4;
    *(__half2*)(yr + permh(c0))     = p0;
    *(__half2*)(yr + permh(c0 + 2)) = p1;
}

// ---- fp16 TC GEMM: 128x128 CTA, 64x32 warp tiles, BK=64, 2-stage, occ2 -----
// Epilogue modes: 0 = fp32 out (+R); 1 = half permh (+gelu opt);
//                 2 = QKV split (Ch=Qe *SCALE, Ch2=Ke, Ch3=Vh);
//                 3 = combined bias-ext: col<1024 -> Qe*fs, else -> Ke (dims 64..127)
#define BK_ 64
#define HSTR 80
#define A_STH (128*HSTR)
#define B_STH (128*HSTR)
#define STGH  (A_STH + B_STH)
#define GEMM_SMEM (2*STGH*2)          // 81920 B

__global__ __launch_bounds__(256, 2) void gemm_tc(
    const __half* __restrict__ A, const __half* __restrict__ Bt,
    const float* __restrict__ bias, const float* __restrict__ R,
    float* __restrict__ Cf, __half* __restrict__ Ch,
    __half* __restrict__ Ch2, __half* __restrict__ Ch3,
    const float* __restrict__ fsp,
    int M, int N, int K, int act, int mode) {
    extern __shared__ __half smh[];
    int tid = threadIdx.x;
    int lane = tid & 31, wid = tid >> 5;
    int wm = wid & 1, wn = wid >> 1;
    int m0 = blockIdx.y * 128, n0 = blockIdx.x * 128;

    float c[4][4][4];
    #pragma unroll
    for (int mi = 0; mi < 4; mi++)
        #pragma unroll
        for (int ni = 0; ni < 4; ni++)
            #pragma unroll
            for (int q = 0; q < 4; q++) c[mi][ni][q] = 0.f;

    int NT = K / BK_;
    auto issue = [&](int t) {
        __half* As = smh + (t & 1) * STGH;
        __half* Bs = As + A_STH;
        int k0 = t * BK_;
        #pragma unroll
        for (int it = 0; it < 4; it++) {
            int i = tid + it * 256;
            int row = i >> 3, off = (i & 7) * 8;
            cp16(As + row * HSTR + off, A + (size_t)(m0 + row) * K + k0 + off);
            cp16(Bs + row * HSTR + off, Bt + (size_t)(n0 + row) * K + k0 + off);
        }
        asm volatile("cp.async.commit_group;");
    };
    issue(0);

    int r = lane >> 2, g = lane & 3;
    for (int t = 0; t < NT; t++) {
        asm volatile("cp.async.wait_group 0;");
        __syncthreads();
        if (t + 1 < NT) issue(t + 1);

        const __half* As = smh + (t & 1) * STGH;
        const __half* Bs = As + A_STH;
        #pragma unroll
        for (int ks = 0; ks < 4; ks++) {
            uint2 alo[4], ahi[4], bb[4];
            #pragma unroll
            for (int mi = 0; mi < 4; mi++) {
                alo[mi] = ((const uint2*)(As + (wm * 64 + mi * 16 + r) * HSTR))[ks * 4 + g];
                ahi[mi] = ((const uint2*)(As + (wm * 64 + mi * 16 + r + 8) * HSTR))[ks * 4 + g];
            }
            #pragma unroll
            for (int ni = 0; ni < 4; ni++)
                bb[ni] = ((const uint2*)(Bs + (wn * 32 + ni * 8 + r) * HSTR))[ks * 4 + g];
            #pragma unroll
            for (int mi = 0; mi < 4; mi++)
                #pragma unroll
                for (int ni = 0; ni < 4; ni++)
                    MMA_F16(c[mi][ni][0], c[mi][ni][1], c[mi][ni][2], c[mi][ni][3],
                            alo[mi].x, ahi[mi].x, alo[mi].y, ahi[mi].y,
                            bb[ni].x, bb[ni].y);
        }
    }

    float fs = fsp ? fsp[0] : 1.0f;
    #pragma unroll
    for (int mi = 0; mi < 4; mi++) {
        int row0 = m0 + wm * 64 + mi * 16 + r;
        #pragma unroll
        for (int ni = 0; ni < 4; ni++) {
            int col = n0 + wn * 32 + ni * 8 + g * 2;
            float b0 = bias[col], b1 = bias[col + 1];
            #pragma unroll
            for (int half_ = 0; half_ < 2; half_++) {
                int row = row0 + half_ * 8;
                float v0 = c[mi][ni][half_ * 2 + 0] + b0;
                float v1 = c[mi][ni][half_ * 2 + 1] + b1;
                if (act == 1) { v0 = gelu_exact(v0); v1 = gelu_exact(v1); }
                if (mode == 0) {
                    if (R) {
                        v0 += R[(size_t)row * N + col];
                        v1 += R[(size_t)row * N + col + 1];
                    }
                    *(float2*)(Cf + (size_t)row * N + col) = make_float2(v0, v1);
                } else if (mode == 1) {
                    *(__half2*)(Ch + (size_t)row * N + permh(col)) = __floats2half2_rn(v0, v1);
                } else if (mode == 2) {
                    int part = col >> 10, cc = col & 1023, h = cc >> 6, d = cc & 63;
                    int bb_ = row >> 11, l = row & 2047;
                    size_t base = (size_t)(bb_ * 16 + h) * L_ + l;
                    if (part == 0)
                        *(__half2*)(Ch + base * 128 + permh(d)) =
                            __floats2half2_rn(SCALE_ * v0, SCALE_ * v1);
                    else if (part == 1)
                        *(__half2*)(Ch2 + base * 128 + permh(d)) = __floats2half2_rn(v0, v1);
                    else
                        *(__half2*)(Ch3 + base * 64 + d) = __floats2half2_rn(v0, v1);
                } else {   // mode 3: combined qb|kb bias-ext into dims 64..127
                    int which = col >> 10, cc = col & 1023, h = cc >> 6, d = cc & 63;
                    int bb_ = row >> 11, l = row & 2047;
                    size_t base = (size_t)(bb_ * 16 + h) * L_ + l;
                    if (which == 0)
                        *(__half2*)(Ch + base * 128 + permh(64 + d)) =
                            __floats2half2_rn(fs * v0, fs * v1);
                    else
                        *(__half2*)(Ch2 + base * 128 + permh(64 + d)) =
                            __floats2half2_rn(v0, v1);
                }
            }
        }
    }
}

// ------- V transpose stager: Vh [bh][l][64] -> Vt [bh][64][L] (l permh'd) ---
__global__ void vtrans_kernel(const __half* __restrict__ Vh, __half* __restrict__ Vt) {
    __shared__ __half vstage[64 * 72];
    int bh = blockIdx.y, l0 = blockIdx.x * 64, tid = threadIdx.x;
    int r = tid >> 2, q4 = tid & 3;
    const __half* src = Vh + ((size_t)bh * L_ + l0 + r) * 64 + q4 * 16;
    int lpos = permh(r);
    #pragma unroll
    for (int dd = 0; dd < 16; dd++)
        vstage[(q4 * 16 + dd) * 72 + lpos] = src[dd];
    __syncthreads();
    for (int i = tid; i < 64 * 8; i += 256) {
        int d = i >> 3, ch = i & 7;
        *(uint4*)(Vt + ((size_t)bh * 64 + d) * L_ + l0 + ch * 8) =
            *(const uint4*)(vstage + d * 72 + ch * 8);
    }
}

// ---------- fp16 tensor-core flash attention, D_qk=128, D_v=64 --------------
#define QSTRH 144
#define KSTRH 144
#define VSTRH 80
#define PSTRH 80
#define ATTN_SMEM ((128*QSTRH + 2*64*KSTRH + 2*64*VSTRH) * 2)   // 94208 B
__global__ __launch_bounds__(256, 1) void attn_tc(
    const __half* __restrict__ Qe, const __half* __restrict__ Ke,
    const __half* __restrict__ Vt, __half* __restrict__ O) {
    extern __shared__ __half smh[];
    __half* Qs  = smh;
    __half* Ks0 = smh + 128 * QSTRH;
    __half* Vs0 = Ks0 + 2 * 64 * KSTRH;
    int qt = blockIdx.x, bh = blockIdx.y;
    int tid = threadIdx.x, lane = tid & 31, wid = tid >> 5;
    int r = lane >> 2, g = lane & 3;
    const __half* Qp = Qe + ((size_t)bh * L_ + qt * 128) * 128;
    const __half* Kp = Ke + (size_t)bh * L_ * 128;
    const __half* Vp = Vt + (size_t)bh * 64 * L_;

    auto issueKV = [&](int t) {
        __half* Ks = Ks0 + (t & 1) * 64 * KSTRH;
        __half* Vs = Vs0 + (t & 1) * 64 * VSTRH;
        const __half* Kt = Kp + (size_t)t * 64 * 128;
        #pragma unroll
        for (int it = 0; it < 4; it++) {
            int i = tid + it * 256;
            int rr = i >> 4, cc = (i & 15) * 8;
            cp16(Ks + rr * KSTRH + cc, Kt + rr * 128 + cc);
        }
        #pragma unroll
        for (int it = 0; it < 2; it++) {
            int i = tid + it * 256;
            int rr = i >> 3, cc = (i & 7) * 8;
            cp16(Vs + rr * VSTRH + cc, Vp + (size_t)rr * L_ + t * 64 + cc);
        }
        asm volatile("cp.async.commit_group;");
    };
    issueKV(0);

    for (int i = tid; i < 2048; i += 256) {
        int rr = i >> 4, cc = (i & 15) * 8;
        *(uint4*)(Qs + rr * QSTRH + cc) = *(const uint4*)(Qp + rr * 128 + cc);
    }
    __syncthreads();
    uint2 qlo[8], qhi[8];
    int qrb = (wid * 16 + r) * QSTRH;
    #pragma unroll
    for (int ks = 0; ks < 8; ks++) {
        qlo[ks] = *(const uint2*)(Qs + qrb + ks * 16 + 4 * g);
        qhi[ks] = *(const uint2*)(Qs + qrb + 8 * QSTRH + ks * 16 + 4 * g);
    }
    __syncthreads();
    __half* Ps = Qs;

    float o[8][4];
    #pragma unroll
    for (int ni = 0; ni < 8; ni++)
        #pragma unroll
        for (int q = 0; q < 4; q++) o[ni][q] = 0.f;
    float m0 = -1e30f, m1 = -1e30f, l0 = 0.f, l1 = 0.f;

    for (int t = 0; t < L_ / 64; t++) {
        if (t + 1 < L_ / 64) {
            issueKV(t + 1);
            asm volatile("cp.async.wait_group 1;");
        } else {
            asm volatile("cp.async.wait_group 0;");
        }
        __syncthreads();
        const __half* Ks = Ks0 + (t & 1) * 64 * KSTRH;
        const __half* Vs = Vs0 + (t & 1) * 64 * VSTRH;

        float c[8][4];
        #pragma unroll
        for (int ni = 0; ni < 8; ni++)
            #pragma unroll
            for (int q = 0; q < 4; q++) c[ni][q] = 0.f;
        #pragma unroll
        for (int ks = 0; ks < 8; ks++) {
            uint2 bb[8];
            #pragma unroll
            for (int ni = 0; ni < 8; ni++)
                bb[ni] = *(const uint2*)(Ks + (ni * 8 + r) * KSTRH + ks * 16 + 4 * g);
            #pragma unroll
            for (int ni = 0; ni < 8; ni++)
                MMA_F16(c[ni][0], c[ni][1], c[ni][2], c[ni][3],
                        qlo[ks].x, qhi[ks].x, qlo[ks].y, qhi[ks].y,
                        bb[ni].x, bb[ni].y);
        }

        float mx0 = -1e30f, mx1 = -1e30f;
        #pragma unroll
        for (int ni = 0; ni < 8; ni++) {
            mx0 = fmaxf(mx0, fmaxf(c[ni][0], c[ni][1]));
            mx1 = fmaxf(mx1, fmaxf(c[ni][2], c[ni][3]));
        }
        #pragma unroll
        for (int ofs = 1; ofs <= 2; ofs <<= 1) {
            mx0 = fmaxf(mx0, __shfl_xor_sync(0xffffffffu, mx0, ofs));
            mx1 = fmaxf(mx1, __shfl_xor_sync(0xffffffffu, mx1, ofs));
        }
        float mn0 = fmaxf(m0, mx0), mn1 = fmaxf(m1, mx1);
        float al0 = __expf(m0 - mn0), al1 = __expf(m1 - mn1);
        float rs0 = 0.f, rs1 = 0.f;
        int prow0 = (wid * 16 + r) * PSTRH;
        int prow1 = prow0 + 8 * PSTRH;
        #pragma unroll
        for (int ni = 0; ni < 8; ni++) {
            float p0 = __expf(c[ni][0] - mn0);
            float p1 = __expf(c[ni][1] - mn0);
            float p2 = __expf(c[ni][2] - mn1);
            float p3 = __expf(c[ni][3] - mn1);
            rs0 += p0 + p1; rs1 += p2 + p3;
            int pc = permh(ni * 8 + 2 * g);
            *(__half2*)(Ps + prow0 + pc) = __floats2half2_rn(p0, p1);
            *(__half2*)(Ps + prow1 + pc) = __floats2half2_rn(p2, p3);
        }
        #pragma unroll
        for (int ofs = 1; ofs <= 2; ofs <<= 1) {
            rs0 += __shfl_xor_sync(0xffffffffu, rs0, ofs);
            rs1 += __shfl_xor_sync(0xffffffffu, rs1, ofs);
        }
        l0 = l0 * al0 + rs0; l1 = l1 * al1 + rs1;
        m0 = mn0; m1 = mn1;
        #pragma unroll
        for (int ni = 0; ni < 8; ni++) {
            o[ni][0] *= al0; o[ni][1] *= al0;
            o[ni][2] *= al1; o[ni][3] *= al1;
        }
        __syncwarp();

        #pragma unroll
        for (int ks = 0; ks < 4; ks++) {
            uint2 alo = *(const uint2*)(Ps + prow0 + ks * 16 + 4 * g);
            uint2 ahi = *(const uint2*)(Ps + prow1 + ks * 16 + 4 * g);
            uint2 bb[8];
            #pragma unroll
            for (int ni = 0; ni < 8; ni++)
                bb[ni] = *(const uint2*)(Vs + (ni * 8 + r) * VSTRH + ks * 16 + 4 * g);
            #pragma unroll
            for (int ni = 0; ni < 8; ni++)
                MMA_F16(o[ni][0], o[ni][1], o[ni][2], o[ni][3],
                        alo.x, ahi.x, alo.y, ahi.y, bb[ni].x, bb[ni].y);
        }
        __syncthreads();
    }

    int b = bh >> 4, h = bh & 15;
    int l0row = qt * 128 + wid * 16 + r;
    float inv0 = 1.0f / l0, inv1 = 1.0f / l1;
    __half* orow0 = O + (size_t)(b * L_ + l0row) * C_;
    __half* orow1 = O + (size_t)(b * L_ + l0row + 8) * C_;
    #pragma unroll
    for (int ni = 0; ni < 8; ni++) {
        int col = h * 64 + ni * 8 + 2 * g;
        *(__half2*)(orow0 + permh(col)) = __floats2half2_rn(o[ni][0] * inv0, o[ni][1] * inv0);
        *(__half2*)(orow1 + permh(col)) = __floats2half2_rn(o[ni][2] * inv1, o[ni][3] * inv1);
    }
}

// ---------------------------------------------------------------------------
extern "C" void kernel_launch(void* const* d_in, const int* in_sizes, int n_in,
                              void* d_out, int out_size) {
    const float* x        = (const float*)d_in[0];
    const float* freqd    = (const float*)d_in[1];
    const float* qkv_w    = (const float*)d_in[2];
    const float* qkv_b    = (const float*)d_in[3];
    const float* fp_w1    = (const float*)d_in[4];
    const float* fp_b1    = (const float*)d_in[5];
    const float* fp_ln_g  = (const float*)d_in[6];
    const float* fp_ln_b  = (const float*)d_in[7];
    const float* fp_w2    = (const float*)d_in[8];
    const float* fp_b2    = (const float*)d_in[9];
    const float* wq_w     = (const float*)d_in[10];
    const float* wq_b     = (const float*)d_in[11];
    const float* wk_w     = (const float*)d_in[12];
    const float* wk_b     = (const float*)d_in[13];
    const float* out_w    = (const float*)d_in[14];
    const float* out_b    = (const float*)d_in[15];
    const float* n1_g     = (const float*)d_in[16];
    const float* n1_b     = (const float*)d_in[17];
    const float* n2_g     = (const float*)d_in[18];
    const float* n2_b     = (const float*)d_in[19];
    const float* mlp_w1   = (const float*)d_in[20];
    const float* mlp_b1   = (const float*)d_in[21];
    const float* mlp_w2   = (const float*)d_in[22];
    const float* mlp_b2   = (const float*)d_in[23];
    const float* fscale   = (const float*)d_in[24];
    float* out = (float*)d_out;

    __half *p_xn, *p_fbg, *p_Qe, *p_Ke, *p_Vh, *p_Vt, *p_O, *p_xn2, *p_h;
    float *p_xmid, *p_bqk;
    __half *pw_qkv, *pw_out, *pw_m1, *pw_m2, *pw_qkb;
    cudaGetSymbolAddress((void**)&p_xn,   g_xn);
    cudaGetSymbolAddress((void**)&p_fbg,  g_fbg);
    cudaGetSymbolAddress((void**)&p_Qe,   g_Qe);
    cudaGetSymbolAddress((void**)&p_Ke,   g_Ke);
    cudaGetSymbolAddress((void**)&p_Vh,   g_Vh);
    cudaGetSymbolAddress((void**)&p_Vt,   g_Vt);
    cudaGetSymbolAddress((void**)&p_O,    g_O);
    cudaGetSymbolAddress((void**)&p_xmid, g_xmid);
    cudaGetSymbolAddress((void**)&p_xn2,  g_xn2);
    cudaGetSymbolAddress((void**)&p_h,    g_h);
    cudaGetSymbolAddress((void**)&pw_qkv, g_wt_qkv);
    cudaGetSymbolAddress((void**)&pw_out, g_wt_out);
    cudaGetSymbolAddress((void**)&pw_m1,  g_wt_m1);
    cudaGetSymbolAddress((void**)&pw_m2,  g_wt_m2);
    cudaGetSymbolAddress((void**)&pw_qkb, g_wt_qkb);
    cudaGetSymbolAddress((void**)&p_bqk,  g_bqk);

    cudaFuncSetAttribute(gemm_tc, cudaFuncAttributeMaxDynamicSharedMemorySize, GEMM_SMEM);
    cudaFuncSetAttribute(attn_tc, cudaFuncAttributeMaxDynamicSharedMemorySize, ATTN_SMEM);

    // 1. weight transpose + fp16 convert
    wtrans_all<<<T_TOT, dim3(32, 8)>>>(qkv_w, out_w, mlp_w1, mlp_w2,
                                       pw_qkv, pw_out, pw_m1, pw_m2);
    // 2. LN1 -> half permh
    ln_kernel<<<ROWS, 256>>>(x, n1_g, n1_b, p_xn);
    // 3. freq rank-1 + LN + GELU -> half permh
    fb1_kernel<<<ROWS, 256>>>(freqd, fp_w1, fp_b1, fp_ln_g, fp_ln_b, p_fbg);
    // 4. QKV projection, epilogue splits into Qe/Ke/Vh  (PROFILED)
    gemm_tc<<<dim3(3 * C_ / 128, ROWS / 128), 256, GEMM_SMEM>>>(
        p_xn, pw_qkv, qkv_b, nullptr, nullptr, p_Qe, p_Ke, p_Vh, nullptr,
        ROWS, 3 * C_, C_, 0, 2);
    // 5. effective combined freq-bias weights + biases (one prepass)
    weff_kernel<<<dim3(8, 16, 2), 256>>>(fp_w2, fp_b2, wq_w, wq_b, wk_w, wk_b,
                                         pw_qkb, p_bqk);
    // 6. [qb|kb] = fbg @ Wqk_eff -> Qe/Ke dims 64..127 (one GEMM, N=2048)
    gemm_tc<<<dim3(2 * C_ / 128, ROWS / 128), 256, GEMM_SMEM>>>(
        p_fbg, pw_qkb, p_bqk, nullptr, nullptr, p_Qe, p_Ke, nullptr, fscale,
        ROWS, 2 * C_, C_, 0, 3);
    // 7. V transpose
    vtrans_kernel<<<dim3(L_ / 64, B_ * H_), 256>>>(p_Vh, p_Vt);
    // 8. fp16 tensor-core flash attention -> O half permh
    attn_tc<<<dim3(L_ / 128, B_ * H_), 256, ATTN_SMEM>>>(p_Qe, p_Ke, p_Vt, p_O);
    // 9. out projection + residual(x) -> xmid fp32
    gemm_tc<<<dim3(C_ / 128, ROWS / 128), 256, GEMM_SMEM>>>(
        p_O, pw_out, out_b, x, p_xmid, nullptr, nullptr, nullptr, nullptr,
        ROWS, C_, C_, 0, 0);
    // 10. LN2 -> half permh
    ln_kernel<<<ROWS, 256>>>(p_xmid, n2_g, n2_b, p_xn2);
    // 11. MLP up + GELU -> h half permh
    gemm_tc<<<dim3(FF_ / 128, ROWS / 128), 256, GEMM_SMEM>>>(
        p_xn2, pw_m1, mlp_b1, nullptr, nullptr, p_h, nullptr, nullptr, nullptr,
        ROWS, FF_, C_, 1, 1);
    // 12. MLP down + residual(xmid) -> final output fp32
    gemm_tc<<<dim3(C_ / 128, ROWS / 128), 256, GEMM_SMEM>>>(
        p_h, pw_m2, mlp_b2, p_xmid, out, nullptr, nullptr, nullptr, nullptr,
        ROWS, C_, FF_, 0, 0);
}

// round 17
// speedup vs baseline: 1.8897x; 1.0081x over previous
#include <cuda_runtime.h>
#include <cuda_fp16.h>
#include <cstdint>
#include <math.h>

#define B_  2
#define L_  2048
#define C_  1024
#define H_  16
#define HD_ 64
#define FF_ 4096
#define ROWS (B_*L_)          // 4096
#define SCALE_ 0.125f         // 64^-0.5
#define EPS_ 1e-5f

// ---------------- scratch (allocation-free rule: __device__ globals) --------
__device__ __half g_xn  [ROWS*C_];        // LN1 out, half, permh layout
__device__ __half g_fbg [ROWS*C_];        // fb1 out, half, permh
__device__ __half g_Qe  [B_*H_*L_*128];   // half, permh layout
__device__ __half g_Ke  [B_*H_*L_*128];   // half, permh layout
__device__ __half g_Vt  [B_*H_*HD_*L_];   // half, [bh][64][L], permh on l%16
__device__ __half g_O   [ROWS*C_];        // attn out, half, permh
__device__ float  g_xmid[ROWS*C_];        // fp32
__device__ __half g_xn2 [ROWS*C_];        // LN2 out, half, permh
__device__ __half g_h   [ROWS*FF_];       // mlp hidden, half, permh
// transposed half weights [N][K], permh on k
__device__ __half g_wt_qkv[3*C_*C_];
__device__ __half g_wt_out[C_*C_];
__device__ __half g_wt_m1 [FF_*C_];
__device__ __half g_wt_m2 [C_*FF_];
// combined effective freq-bias weights [2C, C] (q rows then k rows), half permh
__device__ __half g_wt_qkb[2*C_*C_];
__device__ float  g_bqk[2*C_];

__device__ __forceinline__ float gelu_exact(float v) {
    return 0.5f * v * (1.0f + erff(v * 0.70710678118654752f));
}
__device__ __forceinline__ void cp16(void* smem_dst, const void* gmem_src) {
    unsigned int s = (unsigned int)__cvta_generic_to_shared(smem_dst);
    asm volatile("cp.async.cg.shared.global [%0], [%1], 16;" :: "r"(s), "l"(gmem_src));
}
// fp16 layout interleave within 16: (2g,2g+1,2g+8,2g+9) contiguous at 4g
__device__ __forceinline__ int permh(int k) {
    return (k & ~15) | (k & 1) | (((k >> 3) & 1) << 1) | (((k >> 1) & 3) << 2);
}
#define MMA_F16(c0,c1,c2,c3,a0,a1,a2,a3,b0,b1) \
    asm volatile("mma.sync.aligned.m16n8k16.row.col.f32.f16.f16.f32 " \
        "{%0,%1,%2,%3}, {%4,%5,%6,%7}, {%8,%9}, {%0,%1,%2,%3};" \
        : "+f"(c0), "+f"(c1), "+f"(c2), "+f"(c3) \
        : "r"(a0), "r"(a1), "r"(a2), "r"(a3), "r"(b0), "r"(b1))

// ------- merged weight transpose + fp16 convert (+permh on k) ---------------
#define T_QKV (32*96)
#define T_OUT (32*32)
#define T_M1  (32*128)
#define T_M2  (128*32)
#define T_TOT (T_QKV + T_OUT + T_M1 + T_M2)
__global__ void wtrans_all(const float* __restrict__ qkv_w, const float* __restrict__ out_w,
                           const float* __restrict__ m1_w, const float* __restrict__ m2_w,
                           __half* __restrict__ t_qkv, __half* __restrict__ t_out,
                           __half* __restrict__ t_m1, __half* __restrict__ t_m2) {
    __shared__ float t[32][33];
    int bid = blockIdx.x;
    const float* W; __half* Wt; int K, N, tile;
    if (bid < T_QKV)                    { W = qkv_w; Wt = t_qkv; K = C_;  N = 3*C_; tile = bid; }
    else if ((bid -= T_QKV) < T_OUT)    { W = out_w; Wt = t_out; K = C_;  N = C_;   tile = bid; }
    else if ((bid -= T_OUT) < T_M1)     { W = m1_w;  Wt = t_m1;  K = C_;  N = FF_;  tile = bid; }
    else { bid -= T_M1;                   W = m2_w;  Wt = t_m2;  K = FF_; N = C_;   tile = bid; }
    int ntiles_n = N / 32;
    int k0 = (tile / ntiles_n) * 32;
    int n0 = (tile % ntiles_n) * 32;
    int tx = threadIdx.x, ty = threadIdx.y;
    #pragma unroll
    for (int j = 0; j < 4; j++) {
        int k = k0 + ty + j * 8;
        t[ty + j * 8][tx] = W[(size_t)k * N + n0 + tx];
    }
    __syncthreads();
    int kdst = permh(k0 + tx);
    #pragma unroll
    for (int j = 0; j < 4; j++) {
        int nn = n0 + ty + j * 8;
        Wt[(size_t)nn * K + kdst] = __float2half_rn(t[tx][ty + j * 8]);
    }
}

// ------- effective freq weights (combined q|k) + effective biases -----------
__global__ void weff_kernel(const float* __restrict__ fp_w2, const float* __restrict__ fp_b2,
                            const float* __restrict__ wq_w, const float* __restrict__ wq_b,
                            const float* __restrict__ wk_w, const float* __restrict__ wk_b,
                            __half* __restrict__ Wqkb, float* __restrict__ bqk) {
    __shared__ float sw[64 * 64];
    int et = blockIdx.x, h = blockIdx.y, which = blockIdx.z;
    const float* Wsm = which ? wk_w : wq_w;
    int tid = threadIdx.x;
    for (int i = tid; i < 4096; i += 256) sw[i] = Wsm[i];
    __syncthreads();
    int d = tid & 63, eg = tid >> 6;
    __half* Out = Wqkb + (size_t)which * C_ * C_;
    for (int ee = 0; ee < 32; ee++) {
        int e = et * 128 + eg * 32 + ee;
        const float* w2row = fp_w2 + (size_t)e * C_ + h * 64;
        float acc = 0.f;
        #pragma unroll 8
        for (int e2 = 0; e2 < 64; e2++) acc += w2row[e2] * sw[e2 * 64 + d];
        Out[(size_t)(h * 64 + d) * C_ + permh(e)] = __float2half_rn(acc);
    }
    if (et == 0 && eg == 0) {
        const float* wb = which ? wk_b : wq_b;
        float a = wb[d];
        for (int e2 = 0; e2 < 64; e2++)
            a += fp_b2[h * 64 + e2] * sw[e2 * 64 + d];
        bqk[which * C_ + h * 64 + d] = a;
    }
}

// ---------------- LayerNorm -> half, permh layout ---------------------------
__global__ void ln_kernel(const float* __restrict__ X, const float* __restrict__ g,
                          const float* __restrict__ b, __half* __restrict__ Y) {
    int row = blockIdx.x;
    int tid = threadIdx.x;
    const float4* xr = (const float4*)(X + (size_t)row * C_);
    float4 t = xr[tid];
    float s  = t.x + t.y + t.z + t.w;
    float sq = t.x*t.x + t.y*t.y + t.z*t.z + t.w*t.w;
    #pragma unroll
    for (int o = 16; o; o >>= 1) {
        s  += __shfl_xor_sync(0xffffffffu, s,  o);
        sq += __shfl_xor_sync(0xffffffffu, sq, o);
    }
    __shared__ float ws[8], wq[8];
    __shared__ float mean_s, rstd_s;
    int w = tid >> 5;
    if ((tid & 31) == 0) { ws[w] = s; wq[w] = sq; }
    __syncthreads();
    if (tid == 0) {
        float S = 0.f, Q = 0.f;
        #pragma unroll
        for (int i = 0; i < 8; i++) { S += ws[i]; Q += wq[i]; }
        float mean = S * (1.0f / C_);
        float var  = Q * (1.0f / C_) - mean * mean;
        mean_s = mean; rstd_s = rsqrtf(var + EPS_);
    }
    __syncthreads();
    float mean = mean_s, rstd = rstd_s;
    float4 gg = ((const float4*)g)[tid];
    float4 bb = ((const float4*)b)[tid];
    __half2 p0 = __floats2half2_rn((t.x - mean) * rstd * gg.x + bb.x,
                                   (t.y - mean) * rstd * gg.y + bb.y);
    __half2 p1 = __floats2half2_rn((t.z - mean) * rstd * gg.z + bb.z,
                                   (t.w - mean) * rstd * gg.w + bb.w);
    __half* yr = Y + (size_t)row * C_;
    int c0 = tid * 4;
    *(__half2*)(yr + permh(c0))     = p0;
    *(__half2*)(yr + permh(c0 + 2)) = p1;
}

// ------- freq path stage 1: rank-1 outer + LN + GELU -> half permh ----------
__global__ void fb1_kernel(const float* __restrict__ fd, const float* __restrict__ w1,
                           const float* __restrict__ b1, const float* __restrict__ g,
                           const float* __restrict__ bln, __half* __restrict__ Y) {
    int row = blockIdx.x;
    int tid = threadIdx.x;
    float f = fd[row];
    float4 w = ((const float4*)w1)[tid];
    float4 bb = ((const float4*)b1)[tid];
    float4 t;
    t.x = f * w.x + bb.x; t.y = f * w.y + bb.y;
    t.z = f * w.z + bb.z; t.w = f * w.w + bb.w;
    float s  = t.x + t.y + t.z + t.w;
    float sq = t.x*t.x + t.y*t.y + t.z*t.z + t.w*t.w;
    #pragma unroll
    for (int o = 16; o; o >>= 1) {
        s  += __shfl_xor_sync(0xffffffffu, s,  o);
        sq += __shfl_xor_sync(0xffffffffu, sq, o);
    }
    __shared__ float ws[8], wqs[8];
    __shared__ float mean_s, rstd_s;
    int w5 = tid >> 5;
    if ((tid & 31) == 0) { ws[w5] = s; wqs[w5] = sq; }
    __syncthreads();
    if (tid == 0) {
        float S = 0.f, Q = 0.f;
        #pragma unroll
        for (int i = 0; i < 8; i++) { S += ws[i]; Q += wqs[i]; }
        float mean = S * (1.0f / C_);
        float var  = Q * (1.0f / C_) - mean * mean;
        mean_s = mean; rstd_s = rsqrtf(var + EPS_);
    }
    __syncthreads();
    float mean = mean_s, rstd = rstd_s;
    float4 gg = ((const float4*)g)[tid];
    float4 bl = ((const float4*)bln)[tid];
    __half2 p0 = __floats2half2_rn(gelu_exact((t.x - mean) * rstd * gg.x + bl.x),
                                   gelu_exact((t.y - mean) * rstd * gg.y + bl.y));
    __half2 p1 = __floats2half2_rn(gelu_exact((t.z - mean) * rstd * gg.z + bl.z),
                                   gelu_exact((t.w - mean) * rstd * gg.w + bl.w));
    __half* yr = Y + (size_t)row * C_;
    int c0 = tid * 4;
    *(__half2*)(yr + permh(c0))     = p0;
    *(__half2*)(yr + permh(c0 + 2)) = p1;
}

// ---- fp16 TC GEMM: 128x128 CTA, 64x32 warp tiles, BK=64, 2-stage, occ2 -----
// Epilogue modes: 0 = fp32 out (+R); 1 = half permh (+gelu opt);
//                 2 = QKV split (Ch=Qe *SCALE, Ch2=Ke, Ch3=Vt transposed in-epilogue);
//                 3 = combined bias-ext: col<1024 -> Qe*fs, else -> Ke (dims 64..127)
#define BK_ 64
#define HSTR 80
#define A_STH (128*HSTR)
#define B_STH (128*HSTR)
#define STGH  (A_STH + B_STH)
#define GEMM_SMEM (2*STGH*2)          // 81920 B
#define VSTG 136                      // V transpose stage stride (halves)

__global__ __launch_bounds__(256, 2) void gemm_tc(
    const __half* __restrict__ A, const __half* __restrict__ Bt,
    const float* __restrict__ bias, const float* __restrict__ R,
    float* __restrict__ Cf, __half* __restrict__ Ch,
    __half* __restrict__ Ch2, __half* __restrict__ Ch3,
    const float* __restrict__ fsp,
    int M, int N, int K, int act, int mode) {
    extern __shared__ __half smh[];
    int tid = threadIdx.x;
    int lane = tid & 31, wid = tid >> 5;
    int wm = wid & 1, wn = wid >> 1;
    int m0 = blockIdx.y * 128, n0 = blockIdx.x * 128;

    float c[4][4][4];
    #pragma unroll
    for (int mi = 0; mi < 4; mi++)
        #pragma unroll
        for (int ni = 0; ni < 4; ni++)
            #pragma unroll
            for (int q = 0; q < 4; q++) c[mi][ni][q] = 0.f;

    int NT = K / BK_;
    auto issue = [&](int t) {
        __half* As = smh + (t & 1) * STGH;
        __half* Bs = As + A_STH;
        int k0 = t * BK_;
        #pragma unroll
        for (int it = 0; it < 4; it++) {
            int i = tid + it * 256;
            int row = i >> 3, off = (i & 7) * 8;
            cp16(As + row * HSTR + off, A + (size_t)(m0 + row) * K + k0 + off);
            cp16(Bs + row * HSTR + off, Bt + (size_t)(n0 + row) * K + k0 + off);
        }
        asm volatile("cp.async.commit_group;");
    };
    issue(0);

    int r = lane >> 2, g = lane & 3;
    for (int t = 0; t < NT; t++) {
        asm volatile("cp.async.wait_group 0;");
        __syncthreads();
        if (t + 1 < NT) issue(t + 1);

        const __half* As = smh + (t & 1) * STGH;
        const __half* Bs = As + A_STH;
        #pragma unroll
        for (int ks = 0; ks < 4; ks++) {
            uint2 alo[4], ahi[4], bb[4];
            #pragma unroll
            for (int mi = 0; mi < 4; mi++) {
                alo[mi] = ((const uint2*)(As + (wm * 64 + mi * 16 + r) * HSTR))[ks * 4 + g];
                ahi[mi] = ((const uint2*)(As + (wm * 64 + mi * 16 + r + 8) * HSTR))[ks * 4 + g];
            }
            #pragma unroll
            for (int ni = 0; ni < 4; ni++)
                bb[ni] = ((const uint2*)(Bs + (wn * 32 + ni * 8 + r) * HSTR))[ks * 4 + g];
            #pragma unroll
            for (int mi = 0; mi < 4; mi++)
                #pragma unroll
                for (int ni = 0; ni < 4; ni++)
                    MMA_F16(c[mi][ni][0], c[mi][ni][1], c[mi][ni][2], c[mi][ni][3],
                            alo[mi].x, ahi[mi].x, alo[mi].y, ahi[mi].y,
                            bb[ni].x, bb[ni].y);
        }
    }

    // ---- V-part of QKV GEMM: stage transposed in freed smem, write Vt ----
    if (mode == 2 && n0 >= 2 * C_) {
        __syncthreads();                 // all warps done reading GEMM smem
        __half* vst = smh;               // [128 cols][VSTG]
        #pragma unroll
        for (int mi = 0; mi < 4; mi++) {
            #pragma unroll
            for (int ni = 0; ni < 4; ni++) {
                int lc = wn * 32 + ni * 8 + g * 2;       // local col 0..127
                float b0 = bias[n0 + lc], b1 = bias[n0 + lc + 1];
                #pragma unroll
                for (int half_ = 0; half_ < 2; half_++) {
                    int lrow = wm * 64 + mi * 16 + r + half_ * 8;   // local row 0..127
                    int lpos = permh(lrow);
                    vst[lc * VSTG + lpos]       = __float2half_rn(c[mi][ni][half_ * 2 + 0] + b0);
                    vst[(lc + 1) * VSTG + lpos] = __float2half_rn(c[mi][ni][half_ * 2 + 1] + b1);
                }
            }
        }
        __syncthreads();
        int bb_ = m0 >> 11, l0v = m0 & 2047;
        int vbase = n0 - 2 * C_;
        for (int i = tid; i < 128 * 16; i += 256) {
            int lc = i >> 4, ch = i & 15;
            int vcol = vbase + lc, h = vcol >> 6, d = vcol & 63;
            *(uint4*)(Ch3 + ((size_t)(bb_ * 16 + h) * 64 + d) * L_ + l0v + ch * 8) =
                *(const uint4*)(vst + lc * VSTG + ch * 8);
        }
        return;
    }

    float fs = fsp ? fsp[0] : 1.0f;
    #pragma unroll
    for (int mi = 0; mi < 4; mi++) {
        int row0 = m0 + wm * 64 + mi * 16 + r;
        #pragma unroll
        for (int ni = 0; ni < 4; ni++) {
            int col = n0 + wn * 32 + ni * 8 + g * 2;
            float b0 = bias[col], b1 = bias[col + 1];
            #pragma unroll
            for (int half_ = 0; half_ < 2; half_++) {
                int row = row0 + half_ * 8;
                float v0 = c[mi][ni][half_ * 2 + 0] + b0;
                float v1 = c[mi][ni][half_ * 2 + 1] + b1;
                if (act == 1) { v0 = gelu_exact(v0); v1 = gelu_exact(v1); }
                if (mode == 0) {
                    if (R) {
                        v0 += R[(size_t)row * N + col];
                        v1 += R[(size_t)row * N + col + 1];
                    }
                    *(float2*)(Cf + (size_t)row * N + col) = make_float2(v0, v1);
                } else if (mode == 1) {
                    *(__half2*)(Ch + (size_t)row * N + permh(col)) = __floats2half2_rn(v0, v1);
                } else if (mode == 2) {
                    int part = col >> 10, cc = col & 1023, h = cc >> 6, d = cc & 63;
                    int bb_ = row >> 11, l = row & 2047;
                    size_t base = (size_t)(bb_ * 16 + h) * L_ + l;
                    if (part == 0)
                        *(__half2*)(Ch + base * 128 + permh(d)) =
                            __floats2half2_rn(SCALE_ * v0, SCALE_ * v1);
                    else
                        *(__half2*)(Ch2 + base * 128 + permh(d)) = __floats2half2_rn(v0, v1);
                } else {   // mode 3: combined qb|kb bias-ext into dims 64..127
                    int which = col >> 10, cc = col & 1023, h = cc >> 6, d = cc & 63;
                    int bb_ = row >> 11, l = row & 2047;
                    size_t base = (size_t)(bb_ * 16 + h) * L_ + l;
                    if (which == 0)
                        *(__half2*)(Ch + base * 128 + permh(64 + d)) =
                            __floats2half2_rn(fs * v0, fs * v1);
                    else
                        *(__half2*)(Ch2 + base * 128 + permh(64 + d)) =
                            __floats2half2_rn(v0, v1);
                }
            }
        }
    }
}

// ---------- fp16 tensor-core flash attention, D_qk=128, D_v=64 --------------
#define QSTRH 144
#define KSTRH 144
#define VSTRH 80
#define PSTRH 80
#define ATTN_SMEM ((128*QSTRH + 2*64*KSTRH + 2*64*VSTRH) * 2)   // 94208 B
__global__ __launch_bounds__(256, 1) void attn_tc(
    const __half* __restrict__ Qe, const __half* __restrict__ Ke,
    const __half* __restrict__ Vt, __half* __restrict__ O) {
    extern __shared__ __half smh[];
    __half* Qs  = smh;
    __half* Ks0 = smh + 128 * QSTRH;
    __half* Vs0 = Ks0 + 2 * 64 * KSTRH;
    int qt = blockIdx.x, bh = blockIdx.y;
    int tid = threadIdx.x, lane = tid & 31, wid = tid >> 5;
    int r = lane >> 2, g = lane & 3;
    const __half* Qp = Qe + ((size_t)bh * L_ + qt * 128) * 128;
    const __half* Kp = Ke + (size_t)bh * L_ * 128;
    const __half* Vp = Vt + (size_t)bh * 64 * L_;

    auto issueKV = [&](int t) {
        __half* Ks = Ks0 + (t & 1) * 64 * KSTRH;
        __half* Vs = Vs0 + (t & 1) * 64 * VSTRH;
        const __half* Kt = Kp + (size_t)t * 64 * 128;
        #pragma unroll
        for (int it = 0; it < 4; it++) {
            int i = tid + it * 256;
            int rr = i >> 4, cc = (i & 15) * 8;
            cp16(Ks + rr * KSTRH + cc, Kt + rr * 128 + cc);
        }
        #pragma unroll
        for (int it = 0; it < 2; it++) {
            int i = tid + it * 256;
            int rr = i >> 3, cc = (i & 7) * 8;
            cp16(Vs + rr * VSTRH + cc, Vp + (size_t)rr * L_ + t * 64 + cc);
        }
        asm volatile("cp.async.commit_group;");
    };
    issueKV(0);

    for (int i = tid; i < 2048; i += 256) {
        int rr = i >> 4, cc = (i & 15) * 8;
        *(uint4*)(Qs + rr * QSTRH + cc) = *(const uint4*)(Qp + rr * 128 + cc);
    }
    __syncthreads();
    uint2 qlo[8], qhi[8];
    int qrb = (wid * 16 + r) * QSTRH;
    #pragma unroll
    for (int ks = 0; ks < 8; ks++) {
        qlo[ks] = *(const uint2*)(Qs + qrb + ks * 16 + 4 * g);
        qhi[ks] = *(const uint2*)(Qs + qrb + 8 * QSTRH + ks * 16 + 4 * g);
    }
    __syncthreads();
    __half* Ps = Qs;

    float o[8][4];
    #pragma unroll
    for (int ni = 0; ni < 8; ni++)
        #pragma unroll
        for (int q = 0; q < 4; q++) o[ni][q] = 0.f;
    float m0 = -1e30f, m1 = -1e30f, l0 = 0.f, l1 = 0.f;

    for (int t = 0; t < L_ / 64; t++) {
        if (t + 1 < L_ / 64) {
            issueKV(t + 1);
            asm volatile("cp.async.wait_group 1;");
        } else {
            asm volatile("cp.async.wait_group 0;");
        }
        __syncthreads();
        const __half* Ks = Ks0 + (t & 1) * 64 * KSTRH;
        const __half* Vs = Vs0 + (t & 1) * 64 * VSTRH;

        float c[8][4];
        #pragma unroll
        for (int ni = 0; ni < 8; ni++)
            #pragma unroll
            for (int q = 0; q < 4; q++) c[ni][q] = 0.f;
        #pragma unroll
        for (int ks = 0; ks < 8; ks++) {
            uint2 bb[8];
            #pragma unroll
            for (int ni = 0; ni < 8; ni++)
                bb[ni] = *(const uint2*)(Ks + (ni * 8 + r) * KSTRH + ks * 16 + 4 * g);
            #pragma unroll
            for (int ni = 0; ni < 8; ni++)
                MMA_F16(c[ni][0], c[ni][1], c[ni][2], c[ni][3],
                        qlo[ks].x, qhi[ks].x, qlo[ks].y, qhi[ks].y,
                        bb[ni].x, bb[ni].y);
        }

        float mx0 = -1e30f, mx1 = -1e30f;
        #pragma unroll
        for (int ni = 0; ni < 8; ni++) {
            mx0 = fmaxf(mx0, fmaxf(c[ni][0], c[ni][1]));
            mx1 = fmaxf(mx1, fmaxf(c[ni][2], c[ni][3]));
        }
        #pragma unroll
        for (int ofs = 1; ofs <= 2; ofs <<= 1) {
            mx0 = fmaxf(mx0, __shfl_xor_sync(0xffffffffu, mx0, ofs));
            mx1 = fmaxf(mx1, __shfl_xor_sync(0xffffffffu, mx1, ofs));
        }
        float mn0 = fmaxf(m0, mx0), mn1 = fmaxf(m1, mx1);
        float al0 = __expf(m0 - mn0), al1 = __expf(m1 - mn1);
        float rs0 = 0.f, rs1 = 0.f;
        int prow0 = (wid * 16 + r) * PSTRH;
        int prow1 = prow0 + 8 * PSTRH;
        #pragma unroll
        for (int ni = 0; ni < 8; ni++) {
            float p0 = __expf(c[ni][0] - mn0);
            float p1 = __expf(c[ni][1] - mn0);
            float p2 = __expf(c[ni][2] - mn1);
            float p3 = __expf(c[ni][3] - mn1);
            rs0 += p0 + p1; rs1 += p2 + p3;
            int pc = permh(ni * 8 + 2 * g);
            *(__half2*)(Ps + prow0 + pc) = __floats2half2_rn(p0, p1);
            *(__half2*)(Ps + prow1 + pc) = __floats2half2_rn(p2, p3);
        }
        #pragma unroll
        for (int ofs = 1; ofs <= 2; ofs <<= 1) {
            rs0 += __shfl_xor_sync(0xffffffffu, rs0, ofs);
            rs1 += __shfl_xor_sync(0xffffffffu, rs1, ofs);
        }
        l0 = l0 * al0 + rs0; l1 = l1 * al1 + rs1;
        m0 = mn0; m1 = mn1;
        #pragma unroll
        for (int ni = 0; ni < 8; ni++) {
            o[ni][0] *= al0; o[ni][1] *= al0;
            o[ni][2] *= al1; o[ni][3] *= al1;
        }
        __syncwarp();

        #pragma unroll
        for (int ks = 0; ks < 4; ks++) {
            uint2 alo = *(const uint2*)(Ps + prow0 + ks * 16 + 4 * g);
            uint2 ahi = *(const uint2*)(Ps + prow1 + ks * 16 + 4 * g);
            uint2 bb[8];
            #pragma unroll
            for (int ni = 0; ni < 8; ni++)
                bb[ni] = *(const uint2*)(Vs + (ni * 8 + r) * VSTRH + ks * 16 + 4 * g);
            #pragma unroll
            for (int ni = 0; ni < 8; ni++)
                MMA_F16(o[ni][0], o[ni][1], o[ni][2], o[ni][3],
                        alo.x, ahi.x, alo.y, ahi.y, bb[ni].x, bb[ni].y);
        }
        __syncthreads();
    }

    int b = bh >> 4, h = bh & 15;
    int l0row = qt * 128 + wid * 16 + r;
    float inv0 = 1.0f / l0, inv1 = 1.0f / l1;
    __half* orow0 = O + (size_t)(b * L_ + l0row) * C_;
    __half* orow1 = O + (size_t)(b * L_ + l0row + 8) * C_;
    #pragma unroll
    for (int ni = 0; ni < 8; ni++) {
        int col = h * 64 + ni * 8 + 2 * g;
        *(__half2*)(orow0 + permh(col)) = __floats2half2_rn(o[ni][0] * inv0, o[ni][1] * inv0);
        *(__half2*)(orow1 + permh(col)) = __floats2half2_rn(o[ni][2] * inv1, o[ni][3] * inv1);
    }
}

// ---------------------------------------------------------------------------
extern "C" void kernel_launch(void* const* d_in, const int* in_sizes, int n_in,
                              void* d_out, int out_size) {
    const float* x        = (const float*)d_in[0];
    const float* freqd    = (const float*)d_in[1];
    const float* qkv_w    = (const float*)d_in[2];
    const float* qkv_b    = (const float*)d_in[3];
    const float* fp_w1    = (const float*)d_in[4];
    const float* fp_b1    = (const float*)d_in[5];
    const float* fp_ln_g  = (const float*)d_in[6];
    const float* fp_ln_b  = (const float*)d_in[7];
    const float* fp_w2    = (const float*)d_in[8];
    const float* fp_b2    = (const float*)d_in[9];
    const float* wq_w     = (const float*)d_in[10];
    const float* wq_b     = (const float*)d_in[11];
    const float* wk_w     = (const float*)d_in[12];
    const float* wk_b     = (const float*)d_in[13];
    const float* out_w    = (const float*)d_in[14];
    const float* out_b    = (const float*)d_in[15];
    const float* n1_g     = (const float*)d_in[16];
    const float* n1_b     = (const float*)d_in[17];
    const float* n2_g     = (const float*)d_in[18];
    const float* n2_b     = (const float*)d_in[19];
    const float* mlp_w1   = (const float*)d_in[20];
    const float* mlp_b1   = (const float*)d_in[21];
    const float* mlp_w2   = (const float*)d_in[22];
    const float* mlp_b2   = (const float*)d_in[23];
    const float* fscale   = (const float*)d_in[24];
    float* out = (float*)d_out;

    __half *p_xn, *p_fbg, *p_Qe, *p_Ke, *p_Vt, *p_O, *p_xn2, *p_h;
    float *p_xmid, *p_bqk;
    __half *pw_qkv, *pw_out, *pw_m1, *pw_m2, *pw_qkb;
    cudaGetSymbolAddress((void**)&p_xn,   g_xn);
    cudaGetSymbolAddress((void**)&p_fbg,  g_fbg);
    cudaGetSymbolAddress((void**)&p_Qe,   g_Qe);
    cudaGetSymbolAddress((void**)&p_Ke,   g_Ke);
    cudaGetSymbolAddress((void**)&p_Vt,   g_Vt);
    cudaGetSymbolAddress((void**)&p_O,    g_O);
    cudaGetSymbolAddress((void**)&p_xmid, g_xmid);
    cudaGetSymbolAddress((void**)&p_xn2,  g_xn2);
    cudaGetSymbolAddress((void**)&p_h,    g_h);
    cudaGetSymbolAddress((void**)&pw_qkv, g_wt_qkv);
    cudaGetSymbolAddress((void**)&pw_out, g_wt_out);
    cudaGetSymbolAddress((void**)&pw_m1,  g_wt_m1);
    cudaGetSymbolAddress((void**)&pw_m2,  g_wt_m2);
    cudaGetSymbolAddress((void**)&pw_qkb, g_wt_qkb);
    cudaGetSymbolAddress((void**)&p_bqk,  g_bqk);

    cudaFuncSetAttribute(gemm_tc, cudaFuncAttributeMaxDynamicSharedMemorySize, GEMM_SMEM);
    cudaFuncSetAttribute(attn_tc, cudaFuncAttributeMaxDynamicSharedMemorySize, ATTN_SMEM);

    // 1. weight transpose + fp16 convert
    wtrans_all<<<T_TOT, dim3(32, 8)>>>(qkv_w, out_w, mlp_w1, mlp_w2,
                                       pw_qkv, pw_out, pw_m1, pw_m2);
    // 2. LN1 -> half permh
    ln_kernel<<<ROWS, 256>>>(x, n1_g, n1_b, p_xn);
    // 3. freq rank-1 + LN + GELU -> half permh
    fb1_kernel<<<ROWS, 256>>>(freqd, fp_w1, fp_b1, fp_ln_g, fp_ln_b, p_fbg);
    // 4. QKV projection, epilogue splits into Qe/Ke and Vt (fused transpose)
    gemm_tc<<<dim3(3 * C_ / 128, ROWS / 128), 256, GEMM_SMEM>>>(
        p_xn, pw_qkv, qkv_b, nullptr, nullptr, p_Qe, p_Ke, p_Vt, nullptr,
        ROWS, 3 * C_, C_, 0, 2);
    // 5. effective combined freq-bias weights + biases (one prepass)
    weff_kernel<<<dim3(8, 16, 2), 256>>>(fp_w2, fp_b2, wq_w, wq_b, wk_w, wk_b,
                                         pw_qkb, p_bqk);
    // 6. [qb|kb] = fbg @ Wqk_eff -> Qe/Ke dims 64..127 (one GEMM, N=2048)
    gemm_tc<<<dim3(2 * C_ / 128, ROWS / 128), 256, GEMM_SMEM>>>(
        p_fbg, pw_qkb, p_bqk, nullptr, nullptr, p_Qe, p_Ke, nullptr, fscale,
        ROWS, 2 * C_, C_, 0, 3);
    // 7. fp16 tensor-core flash attention -> O half permh
    attn_tc<<<dim3(L_ / 128, B_ * H_), 256, ATTN_SMEM>>>(p_Qe, p_Ke, p_Vt, p_O);
    // 8. out projection + residual(x) -> xmid fp32
    gemm_tc<<<dim3(C_ / 128, ROWS / 128), 256, GEMM_SMEM>>>(
        p_O, pw_out, out_b, x, p_xmid, nullptr, nullptr, nullptr, nullptr,
        ROWS, C_, C_, 0, 0);
    // 9. LN2 -> half permh
    ln_kernel<<<ROWS, 256>>>(p_xmid, n2_g, n2_b, p_xn2);
    // 10. MLP up + GELU -> h half permh
    gemm_tc<<<dim3(FF_ / 128, ROWS / 128), 256, GEMM_SMEM>>>(
        p_xn2, pw_m1, mlp_b1, nullptr, nullptr, p_h, nullptr, nullptr, nullptr,
        ROWS, FF_, C_, 1, 1);
    // 11. MLP down + residual(xmid) -> final output fp32
    gemm_tc<<<dim3(C_ / 128, ROWS / 128), 256, GEMM_SMEM>>>(
        p_h, pw_m2, mlp_b2, p_xmid, out, nullptr, nullptr, nullptr, nullptr,
        ROWS, C_, FF_, 0, 0);
}